// round 3
// baseline (speedup 1.0000x reference)
#include <cuda_runtime.h>
#include <cstdint>

#define BATCH 8
#define CIN 3
#define HW 320
#define C1 64
#define PS 10
#define P2 100
#define P2P 104
#define NPATCH 1024
#define IMGS 16

// scratch (device globals — no runtime allocation)
__device__ float g_t1[BATCH*C1*HW*HW];       // conv1 out (210 MB)
__device__ float g_ini[IMGS*HW*HW];
__device__ float g_fea[IMGS*HW*HW];
__device__ float g_M[P2*P2];                 // (W2@W1) row-major [p][k]
__device__ float g_UI[IMGS*NPATCH*P2P];
__device__ float g_UF[IMGS*NPATCH*P2P];

// ---------------- helpers ----------------
__device__ __forceinline__ uint32_t f2tf32(float f) {
    uint32_t r;
    asm("cvt.rna.tf32.f32 %0, %1;" : "=r"(r) : "f"(f));
    return r;
}
__device__ __forceinline__ void mma_tf32(float* d, const uint32_t* a, const uint32_t* b) {
    asm volatile(
        "mma.sync.aligned.m16n8k8.row.col.f32.tf32.tf32.f32 "
        "{%0,%1,%2,%3}, {%4,%5,%6,%7}, {%8,%9}, {%0,%1,%2,%3};"
        : "+f"(d[0]), "+f"(d[1]), "+f"(d[2]), "+f"(d[3])
        : "r"(a[0]), "r"(a[1]), "r"(a[2]), "r"(a[3]), "r"(b[0]), "r"(b[1]));
}

// ---------------- M = w_lin2 @ w_lin1 (row-major [p][k]) ----------------
__global__ void k_buildM(const float* __restrict__ w1, const float* __restrict__ w2) {
    int p = blockIdx.x;
    int k = threadIdx.x;
    if (k >= P2) return;
    float acc = 0.f;
    for (int q = 0; q < 2*P2; ++q)
        acc += w2[p*2*P2 + q] * w1[q*P2 + k];
    g_M[p*P2 + k] = acc;
}

// ---------------- conv1: 7x7, 3->64, pad 3 via mma.sync tf32 ----------------
// CTA: 256 thr, tile 8x16 pixels (M=128), N=64, K=160 (20 chunks of 8)
#define SA_STR 164
#define C1_SMEM ((128*SA_STR + 64*SA_STR + 1008 + 64)*4 + 160*4)

__global__ __launch_bounds__(256) void k_conv1(const float* __restrict__ x,
        const float* __restrict__ w, const float* __restrict__ b) {
    extern __shared__ float smc1[];
    float* sA     = smc1;                     // 128 x 164
    float* sB     = sA + 128*SA_STR;          // 64 x 164
    float* s_in   = sB + 64*SA_STR;           // 3 x 14 x 24
    float* s_bias = s_in + 1008;              // 64
    int*   s_koff = (int*)(s_bias + 64);      // 160

    int tid = threadIdx.x;
    int img = blockIdx.z;
    int oy0 = blockIdx.y*8, ox0 = blockIdx.x*16;

    if (tid < 160) {
        int k = tid, v = -1;
        if (k < 147) { int ci = k/49, r = k - ci*49, kh = r/7, kw = r - kh*7; v = ci*336 + kh*24 + kw; }
        s_koff[k] = v;
    }
    if (tid < C1) s_bias[tid] = b[tid];
    // weights -> sB [oc][k], tf32
    for (int it = tid; it < 64*40; it += 256) {
        int oc = it/40, k0 = (it - oc*40) << 2;
        uint4 u;
        u.x = f2tf32(k0+0 < 147 ? w[oc*147 + k0+0] : 0.f);
        u.y = f2tf32(k0+1 < 147 ? w[oc*147 + k0+1] : 0.f);
        u.z = f2tf32(k0+2 < 147 ? w[oc*147 + k0+2] : 0.f);
        u.w = f2tf32(k0+3 < 147 ? w[oc*147 + k0+3] : 0.f);
        *(uint4*)&sB[oc*SA_STR + k0] = u;
    }
    // input halo patch
    const float* xb = x + img*CIN*HW*HW;
    for (int idx = tid; idx < CIN*14*22; idx += 256) {
        int ci = idx / (14*22); int r = idx - ci*(14*22);
        int iy = r / 22, ix = r - iy*22;
        int gy = oy0 - 3 + iy, gx = ox0 - 3 + ix;
        float v = 0.f;
        if (gy >= 0 && gy < HW && gx >= 0 && gx < HW)
            v = xb[ci*HW*HW + gy*HW + gx];
        s_in[ci*336 + iy*24 + ix] = v;
    }
    __syncthreads();
    // im2col -> sA [pixel][k], tf32
    for (int it = tid; it < 128*40; it += 256) {
        int r = it/40, k0 = (it - r*40) << 2;
        int bofs = (r>>4)*24 + (r&15);
        int4 ko = *(const int4*)&s_koff[k0];
        uint4 u;
        u.x = f2tf32(ko.x >= 0 ? s_in[bofs + ko.x] : 0.f);
        u.y = f2tf32(ko.y >= 0 ? s_in[bofs + ko.y] : 0.f);
        u.z = f2tf32(ko.z >= 0 ? s_in[bofs + ko.z] : 0.f);
        u.w = f2tf32(ko.w >= 0 ? s_in[bofs + ko.w] : 0.f);
        *(uint4*)&sA[r*SA_STR + k0] = u;
    }
    __syncthreads();

    int wid = tid >> 5, lane = tid & 31;
    int m0 = (wid & 3) * 32, n0 = (wid >> 2) * 32;
    float d[2][4][4];
    #pragma unroll
    for (int i = 0; i < 2; ++i)
        #pragma unroll
        for (int j = 0; j < 4; ++j)
            #pragma unroll
            for (int q = 0; q < 4; ++q) d[i][j][q] = 0.f;

    const uint32_t* uA = (const uint32_t*)sA;
    const uint32_t* uB = (const uint32_t*)sB;
    int ar = m0 + (lane >> 2), ac = lane & 3;
    int br = n0 + (lane >> 2);

    #pragma unroll 5
    for (int kc = 0; kc < 20; ++kc) {
        int k0 = kc*8;
        uint32_t a[2][4], bf[4][2];
        #pragma unroll
        for (int i = 0; i < 2; ++i) {
            const uint32_t* base = uA + (ar + 16*i)*SA_STR + k0 + ac;
            a[i][0] = base[0];
            a[i][1] = base[8*SA_STR];
            a[i][2] = base[4];
            a[i][3] = base[8*SA_STR + 4];
        }
        #pragma unroll
        for (int j = 0; j < 4; ++j) {
            const uint32_t* base = uB + (br + 8*j)*SA_STR + k0 + ac;
            bf[j][0] = base[0];
            bf[j][1] = base[4];
        }
        #pragma unroll
        for (int i = 0; i < 2; ++i)
            #pragma unroll
            for (int j = 0; j < 4; ++j)
                mma_tf32(d[i][j], a[i], bf[j]);
    }

    // epilogue: D[row=pixel][col=oc] + bias
    float* ob = g_t1 + (size_t)img*C1*HW*HW;
    #pragma unroll
    for (int i = 0; i < 2; ++i) {
        int r0 = m0 + 16*i + (lane >> 2);
        #pragma unroll
        for (int rr = 0; rr < 2; ++rr) {
            int row = r0 + 8*rr;
            size_t pix = (size_t)(oy0 + (row >> 4))*HW + ox0 + (row & 15);
            #pragma unroll
            for (int j = 0; j < 4; ++j) {
                int c0 = n0 + 8*j + 2*(lane & 3);
                ob[(size_t)c0*HW*HW + pix]     = d[i][j][2*rr + 0] + s_bias[c0];
                ob[(size_t)(c0+1)*HW*HW + pix] = d[i][j][2*rr + 1] + s_bias[c0+1];
            }
        }
    }
}

// ---------------- conv2 (3x3, 64->2, pad 1) + fm (1x1, 3->2, /4) ----------------
__global__ __launch_bounds__(256) void k_conv2_fea(const float* __restrict__ x,
        const float* __restrict__ w2, const float* __restrict__ b2,
        const float* __restrict__ wfm, const float* __restrict__ bfm) {
    __shared__ float s_t[8][34][36];
    __shared__ float s_w[2*C1*9];
    int tx = threadIdx.x, ty = threadIdx.y;
    int tid = ty*16 + tx;
    int bz = blockIdx.z;
    int oy0 = blockIdx.y*32, ox0 = blockIdx.x*32;

    for (int idx = tid; idx < 2*C1*9; idx += 256) s_w[idx] = w2[idx];

    float acc[2][4];
    #pragma unroll
    for (int c = 0; c < 2; ++c)
        #pragma unroll
        for (int j = 0; j < 4; ++j) acc[c][j] = 0.f;

    for (int cc = 0; cc < 8; ++cc) {
        __syncthreads();
        for (int idx = tid; idx < 8*34*34; idx += 256) {
            int ci = idx / (34*34); int r = idx % (34*34);
            int iy = r / 34, ix = r % 34;
            int gy = oy0 - 1 + iy, gx = ox0 - 1 + ix;
            float v = 0.f;
            if (gy >= 0 && gy < HW && gx >= 0 && gx < HW)
                v = g_t1[((bz*C1 + cc*8 + ci)*HW + gy)*HW + gx];
            s_t[ci][iy][ix] = v;
        }
        __syncthreads();
        for (int ci = 0; ci < 8; ++ci) {
            int cidx = cc*8 + ci;
            #pragma unroll
            for (int kh = 0; kh < 3; ++kh)
                #pragma unroll
                for (int kw = 0; kw < 3; ++kw) {
                    float v0 = s_t[ci][ty+kh][tx+kw];
                    float v1 = s_t[ci][ty+kh][tx+16+kw];
                    float v2 = s_t[ci][ty+16+kh][tx+kw];
                    float v3 = s_t[ci][ty+16+kh][tx+16+kw];
                    float w0 = s_w[cidx*9 + kh*3 + kw];
                    float w1 = s_w[576 + cidx*9 + kh*3 + kw];
                    acc[0][0] += v0*w0; acc[0][1] += v1*w0;
                    acc[0][2] += v2*w0; acc[0][3] += v3*w0;
                    acc[1][0] += v0*w1; acc[1][1] += v1*w1;
                    acc[1][2] += v2*w1; acc[1][3] += v3*w1;
                }
        }
    }

    int oys[4] = {oy0+ty, oy0+ty, oy0+ty+16, oy0+ty+16};
    int oxs[4] = {ox0+tx, ox0+tx+16, ox0+tx, ox0+tx+16};
    #pragma unroll
    for (int c = 0; c < 2; ++c) {
        float bb = b2[c];
        float f0 = wfm[c*3+0], f1 = wfm[c*3+1], f2 = wfm[c*3+2], fb = bfm[c];
        #pragma unroll
        for (int j = 0; j < 4; ++j) {
            int o = ((bz*2 + c)*HW + oys[j])*HW + oxs[j];
            g_ini[o] = acc[c][j] + bb;
            int xb = bz*CIN*HW*HW + oys[j]*HW + oxs[j];
            float s = x[xb]*f0 + x[xb + HW*HW]*f1 + x[xb + 2*HW*HW]*f2 + fb;
            g_fea[o] = s * 0.25f;
        }
    }
}

// ---------------- trans: out = relu(M @ v) per patch ----------------
__global__ __launch_bounds__(128) void k_trans() {
    __shared__ float s_M[P2*P2];
    __shared__ float s_Vt[P2][20];
    int tid = threadIdx.x;
    int img = blockIdx.y;
    int l0 = blockIdx.x * 16;
    const float* src = (blockIdx.z == 0) ? g_ini : g_fea;
    float* dst = (blockIdx.z == 0) ? g_UI : g_UF;

    for (int idx = tid; idx < P2*P2; idx += 128) s_M[idx] = g_M[idx];
    for (int idx = tid; idx < 16*P2; idx += 128) {
        int pi = idx / P2, el = idx - pi*P2;
        int l = l0 + pi;
        int ph = l >> 5, pw = l & 31;
        int py = el / PS, px = el - py*PS;
        s_Vt[el][pi] = src[img*HW*HW + (ph*PS + py)*HW + (pw*PS + px)];
    }
    // zero the K-pad (cols 100..103)
    for (int idx = tid; idx < 64; idx += 128) {
        int pi = idx >> 2, pp = idx & 3;
        dst[(size_t)img*NPATCH*P2P + (l0 + pi)*P2P + P2 + pp] = 0.f;
    }
    __syncthreads();

    if (tid < P2) {
        float acc[16];
        #pragma unroll
        for (int i = 0; i < 16; ++i) acc[i] = 0.f;
        const float* Mp = &s_M[tid*P2];
        #pragma unroll 5
        for (int k4 = 0; k4 < 25; ++k4) {
            float4 m4 = *(const float4*)&Mp[k4*4];
            float mm[4] = {m4.x, m4.y, m4.z, m4.w};
            #pragma unroll
            for (int j = 0; j < 4; ++j) {
                const float* vr = s_Vt[k4*4 + j];
                float4 a = *(const float4*)vr;
                float4 bb = *(const float4*)(vr + 4);
                float4 c = *(const float4*)(vr + 8);
                float4 dd = *(const float4*)(vr + 12);
                float mj = mm[j];
                acc[0]  += mj*a.x;  acc[1]  += mj*a.y;  acc[2]  += mj*a.z;  acc[3]  += mj*a.w;
                acc[4]  += mj*bb.x; acc[5]  += mj*bb.y; acc[6]  += mj*bb.z; acc[7]  += mj*bb.w;
                acc[8]  += mj*c.x;  acc[9]  += mj*c.y;  acc[10] += mj*c.z;  acc[11] += mj*c.w;
                acc[12] += mj*dd.x; acc[13] += mj*dd.y; acc[14] += mj*dd.z; acc[15] += mj*dd.w;
            }
        }
        float* db = dst + (size_t)img*NPATCH*P2P + l0*P2P + tid;
        #pragma unroll
        for (int i = 0; i < 16; ++i)
            db[i*P2P] = fmaxf(acc[i], 0.f);
    }
}

// ---------------- att: batched 1024x1024x100 NT-GEMM via mma.sync, /100 ----------------
#define AT_STR 108
#define ATT_SMEM (2*64*AT_STR*4)
__global__ __launch_bounds__(128) void k_att(float* __restrict__ out) {
    extern __shared__ float sma[];
    float* sA = sma;                 // 64 x 108 (UI rows)
    float* sB = sma + 64*AT_STR;     // 64 x 108 (UF rows)
    int tid = threadIdx.x;
    int wid = tid >> 5, lane = tid & 31;
    int img = blockIdx.z;
    int gl0 = blockIdx.y*64, gm0 = blockIdx.x*64;
    const float* UI = g_UI + (size_t)img*NPATCH*P2P;
    const float* UF = g_UF + (size_t)img*NPATCH*P2P;

    for (int it = tid; it < 64*26; it += 128) {
        int rr = it/26, k0 = (it - rr*26) << 2;
        float4 va = *(const float4*)&UI[(size_t)(gl0 + rr)*P2P + k0];
        *(uint4*)&sA[rr*AT_STR + k0] =
            make_uint4(f2tf32(va.x), f2tf32(va.y), f2tf32(va.z), f2tf32(va.w));
        float4 vb = *(const float4*)&UF[(size_t)(gm0 + rr)*P2P + k0];
        *(uint4*)&sB[rr*AT_STR + k0] =
            make_uint4(f2tf32(vb.x), f2tf32(vb.y), f2tf32(vb.z), f2tf32(vb.w));
    }
    __syncthreads();

    int m0 = (wid & 1)*32, n0 = (wid >> 1)*32;
    float d[2][4][4];
    #pragma unroll
    for (int i = 0; i < 2; ++i)
        #pragma unroll
        for (int j = 0; j < 4; ++j)
            #pragma unroll
            for (int q = 0; q < 4; ++q) d[i][j][q] = 0.f;

    const uint32_t* uA = (const uint32_t*)sA;
    const uint32_t* uB = (const uint32_t*)sB;
    int ar = m0 + (lane >> 2), ac = lane & 3;
    int br = n0 + (lane >> 2);

    #pragma unroll
    for (int kc = 0; kc < 13; ++kc) {
        int k0 = kc*8;
        uint32_t a[2][4], bf[4][2];
        #pragma unroll
        for (int i = 0; i < 2; ++i) {
            const uint32_t* base = uA + (ar + 16*i)*AT_STR + k0 + ac;
            a[i][0] = base[0];
            a[i][1] = base[8*AT_STR];
            a[i][2] = base[4];
            a[i][3] = base[8*AT_STR + 4];
        }
        #pragma unroll
        for (int j = 0; j < 4; ++j) {
            const uint32_t* base = uB + (br + 8*j)*AT_STR + k0 + ac;
            bf[j][0] = base[0];
            bf[j][1] = base[4];
        }
        #pragma unroll
        for (int i = 0; i < 2; ++i)
            #pragma unroll
            for (int j = 0; j < 4; ++j)
                mma_tf32(d[i][j], a[i], bf[j]);
    }

    #pragma unroll
    for (int i = 0; i < 2; ++i) {
        #pragma unroll
        for (int rr = 0; rr < 2; ++rr) {
            int l = gl0 + m0 + 16*i + (lane >> 2) + 8*rr;
            #pragma unroll
            for (int j = 0; j < 4; ++j) {
                int m = gm0 + n0 + 8*j + 2*(lane & 3);
                float2 v = make_float2(d[i][j][2*rr + 0]*0.01f, d[i][j][2*rr + 1]*0.01f);
                *(float2*)&out[((long)img*NPATCH + l)*NPATCH + m] = v;
            }
        }
    }
}

extern "C" void kernel_launch(void* const* d_in, const int* in_sizes, int n_in,
                              void* d_out, int out_size) {
    const float* x   = (const float*)d_in[0];
    const float* w1c = (const float*)d_in[1];
    const float* b1c = (const float*)d_in[2];
    const float* w2c = (const float*)d_in[3];
    const float* b2c = (const float*)d_in[4];
    const float* wfm = (const float*)d_in[5];
    const float* bfm = (const float*)d_in[6];
    const float* wl1 = (const float*)d_in[7];
    const float* wl2 = (const float*)d_in[8];
    float* out = (float*)d_out;

    static bool attr_set = false;
    if (!attr_set) {
        cudaFuncSetAttribute(k_conv1, cudaFuncAttributeMaxDynamicSharedMemorySize, C1_SMEM);
        cudaFuncSetAttribute(k_att,   cudaFuncAttributeMaxDynamicSharedMemorySize, ATT_SMEM);
        attr_set = true;
    }

    k_buildM<<<P2, 128>>>(wl1, wl2);
    k_conv1<<<dim3(20,40,BATCH), 256, C1_SMEM>>>(x, w1c, b1c);
    k_conv2_fea<<<dim3(10,10,BATCH), dim3(16,16)>>>(x, w2c, b2c, wfm, bfm);
    k_trans<<<dim3(64, IMGS, 2), 128>>>();
    k_att<<<dim3(16,16,IMGS), 128, ATT_SMEM>>>(out);
}

// round 4
// speedup vs baseline: 1.5704x; 1.5704x over previous
#include <cuda_runtime.h>
#include <cuda_fp16.h>
#include <cstdint>

#define BATCH 8
#define CIN 3
#define HW 320
#define HW2 (HW*HW)
#define C1 64
#define PS 10
#define P2 100
#define P2P 104
#define NPATCH 1024
#define IMGS 16

// scratch (device globals — no runtime allocation)
__device__ __half g_t1h[(size_t)BATCH*C1*HW2];   // conv1 out, fp16 (105 MB)
__device__ float g_ini[IMGS*HW2];
__device__ float g_fea[IMGS*HW2];
__device__ uint32_t g_M[P2*P2];                  // (W2@W1) row-major [p][k], tf32 bits
__device__ float g_UI[(size_t)IMGS*NPATCH*P2P];
__device__ float g_UF[(size_t)IMGS*NPATCH*P2P];

// ---------------- helpers ----------------
__device__ __forceinline__ uint32_t f2tf32(float f) {
    uint32_t r;
    asm("cvt.rna.tf32.f32 %0, %1;" : "=r"(r) : "f"(f));
    return r;
}
__device__ __forceinline__ void mma_tf32(float* d, const uint32_t* a, const uint32_t* b) {
    asm volatile(
        "mma.sync.aligned.m16n8k8.row.col.f32.tf32.tf32.f32 "
        "{%0,%1,%2,%3}, {%4,%5,%6,%7}, {%8,%9}, {%0,%1,%2,%3};"
        : "+f"(d[0]), "+f"(d[1]), "+f"(d[2]), "+f"(d[3])
        : "r"(a[0]), "r"(a[1]), "r"(a[2]), "r"(a[3]), "r"(b[0]), "r"(b[1]));
}

// ---------------- M = w_lin2 @ w_lin1 (row-major [p][k], tf32 bits) ----------------
__global__ void k_buildM(const float* __restrict__ w1, const float* __restrict__ w2) {
    int p = blockIdx.x;
    int k = threadIdx.x;
    if (k >= P2) return;
    float acc = 0.f;
    for (int q = 0; q < 2*P2; ++q)
        acc += w2[p*2*P2 + q] * w1[q*P2 + k];
    g_M[p*P2 + k] = f2tf32(acc);
}

// ---------------- conv1: 7x7, 3->64, pad 3 via mma.sync tf32 ----------------
// CTA 256 thr, tile 8x16 pixels (M=128), N=64, K=160 (20 chunks of 8).
// A fragments built directly from halo tile; epilogue staged via smem, fp16 out.
#define SB_STR 164
#define STG_STR 140
// layout (floats): sB[64*164] | s_in[1008] | bias[64] | koff[160]
#define C1_FL (64*SB_STR + 1008 + 64 + 160)

__global__ __launch_bounds__(256) void k_conv1(const float* __restrict__ x,
        const float* __restrict__ w, const float* __restrict__ b) {
    __shared__ float smc[C1_FL];
    float* sB     = smc;
    float* s_in   = smc + 64*SB_STR;
    float* s_bias = s_in + 1008;
    int*   s_koff = (int*)(s_bias + 64);
    float* stage  = smc;               // aliases sB after MMA (64 x 140)

    int tid = threadIdx.x;
    int img = blockIdx.z;
    int oy0 = blockIdx.y*8, ox0 = blockIdx.x*16;

    if (tid < 160) {
        int k = tid, v = -1;
        if (k < 147) { int ci = k/49, r = k - ci*49, kh = r/7, kw = r - kh*7; v = ci*336 + kh*24 + kw; }
        s_koff[k] = v;
    }
    if (tid < C1) s_bias[tid] = b[tid];
    for (int it = tid; it < 64*40; it += 256) {
        int oc = it/40, k0 = (it - oc*40) << 2;
        uint4 u;
        u.x = f2tf32(k0+0 < 147 ? w[oc*147 + k0+0] : 0.f);
        u.y = f2tf32(k0+1 < 147 ? w[oc*147 + k0+1] : 0.f);
        u.z = f2tf32(k0+2 < 147 ? w[oc*147 + k0+2] : 0.f);
        u.w = f2tf32(k0+3 < 147 ? w[oc*147 + k0+3] : 0.f);
        *(uint4*)&sB[oc*SB_STR + k0] = u;
    }
    const float* xb = x + img*CIN*HW2;
    for (int idx = tid; idx < CIN*14*22; idx += 256) {
        int ci = idx / (14*22); int r = idx - ci*(14*22);
        int iy = r / 22, ix = r - iy*22;
        int gy = oy0 - 3 + iy, gx = ox0 - 3 + ix;
        float v = 0.f;
        if (gy >= 0 && gy < HW && gx >= 0 && gx < HW)
            v = xb[ci*HW2 + gy*HW + gx];
        s_in[ci*336 + iy*24 + ix] = v;
    }
    __syncthreads();

    int wid = tid >> 5, lane = tid & 31;
    int m0 = (wid & 3) * 32, n0 = (wid >> 2) * 32;
    int ac = lane & 3, lq = lane >> 2;
    // the 4 pixel rows this lane touches in A
    int r0 = m0 + lq, r1 = r0 + 8, r2 = r0 + 16, r3 = r0 + 24;
    int bo0 = (r0>>4)*24 + (r0&15);
    int bo1 = (r1>>4)*24 + (r1&15);
    int bo2 = (r2>>4)*24 + (r2&15);
    int bo3 = (r3>>4)*24 + (r3&15);
    int br = n0 + lq;

    float d[2][4][4];
    #pragma unroll
    for (int i = 0; i < 2; ++i)
        #pragma unroll
        for (int j = 0; j < 4; ++j)
            #pragma unroll
            for (int q = 0; q < 4; ++q) d[i][j][q] = 0.f;

    const uint32_t* uB = (const uint32_t*)sB;

    #pragma unroll 4
    for (int kc = 0; kc < 20; ++kc) {
        int k0 = kc*8;
        int ko0 = s_koff[k0 + ac];
        int ko1 = s_koff[k0 + ac + 4];
        uint32_t a[2][4];
        a[0][0] = f2tf32(ko0 >= 0 ? s_in[bo0 + ko0] : 0.f);
        a[0][1] = f2tf32(ko0 >= 0 ? s_in[bo1 + ko0] : 0.f);
        a[0][2] = f2tf32(ko1 >= 0 ? s_in[bo0 + ko1] : 0.f);
        a[0][3] = f2tf32(ko1 >= 0 ? s_in[bo1 + ko1] : 0.f);
        a[1][0] = f2tf32(ko0 >= 0 ? s_in[bo2 + ko0] : 0.f);
        a[1][1] = f2tf32(ko0 >= 0 ? s_in[bo3 + ko0] : 0.f);
        a[1][2] = f2tf32(ko1 >= 0 ? s_in[bo2 + ko1] : 0.f);
        a[1][3] = f2tf32(ko1 >= 0 ? s_in[bo3 + ko1] : 0.f);
        uint32_t bf[4][2];
        #pragma unroll
        for (int j = 0; j < 4; ++j) {
            const uint32_t* base = uB + (br + 8*j)*SB_STR + k0 + ac;
            bf[j][0] = base[0];
            bf[j][1] = base[4];
        }
        #pragma unroll
        for (int i = 0; i < 2; ++i)
            #pragma unroll
            for (int j = 0; j < 4; ++j)
                mma_tf32(d[i][j], a[i], bf[j]);
    }

    // stage D -> smem [oc][pixel], stride 140 (conflict-free)
    __syncthreads();
    #pragma unroll
    for (int i = 0; i < 2; ++i) {
        #pragma unroll
        for (int rr = 0; rr < 2; ++rr) {
            int pix = m0 + 16*i + lq + 8*rr;
            #pragma unroll
            for (int j = 0; j < 4; ++j) {
                int oc = n0 + 8*j + 2*ac;
                stage[oc*STG_STR + pix]     = d[i][j][2*rr + 0];
                stage[(oc+1)*STG_STR + pix] = d[i][j][2*rr + 1];
            }
        }
    }
    __syncthreads();

    // coalesced fp16 store: thread -> oc=tid>>2, part=tid&3 (32 pixels)
    {
        int oc = tid >> 2, part = tid & 3;
        float bb = s_bias[oc];
        __half* ob = g_t1h + (size_t)img*C1*HW2 + (size_t)oc*HW2;
        #pragma unroll
        for (int j = 0; j < 8; ++j) {
            int p0 = part*32 + 4*j;
            float4 v = *(const float4*)&stage[oc*STG_STR + p0];
            __half2 h0 = __floats2half2_rn(v.x + bb, v.y + bb);
            __half2 h1 = __floats2half2_rn(v.z + bb, v.w + bb);
            int py = p0 >> 4, px = p0 & 15;
            __half2* dst = (__half2*)(ob + (size_t)(oy0 + py)*HW + ox0 + px);
            dst[0] = h0;
            dst[1] = h1;
        }
    }
}

// ---------------- conv2 (3x3, 64->2, pad 1, fp16 in) + fm (1x1, 3->2, /4) ----------------
__global__ __launch_bounds__(256) void k_conv2_fea(const float* __restrict__ x,
        const float* __restrict__ w2, const float* __restrict__ b2,
        const float* __restrict__ wfm, const float* __restrict__ bfm) {
    __shared__ float s_t[8][34][36];
    __shared__ float s_w[2*C1*9];
    int tx = threadIdx.x, ty = threadIdx.y;
    int tid = ty*16 + tx;
    int bz = blockIdx.z;
    int oy0 = blockIdx.y*32, ox0 = blockIdx.x*32;

    for (int idx = tid; idx < 2*C1*9; idx += 256) s_w[idx] = w2[idx];

    float acc[2][4];
    #pragma unroll
    for (int c = 0; c < 2; ++c)
        #pragma unroll
        for (int j = 0; j < 4; ++j) acc[c][j] = 0.f;

    for (int cc = 0; cc < 8; ++cc) {
        __syncthreads();
        for (int idx = tid; idx < 8*34*34; idx += 256) {
            int ci = idx / (34*34); int r = idx % (34*34);
            int iy = r / 34, ix = r % 34;
            int gy = oy0 - 1 + iy, gx = ox0 - 1 + ix;
            float v = 0.f;
            if (gy >= 0 && gy < HW && gx >= 0 && gx < HW)
                v = __half2float(g_t1h[((size_t)(bz*C1 + cc*8 + ci))*HW2 + gy*HW + gx]);
            s_t[ci][iy][ix] = v;
        }
        __syncthreads();
        for (int ci = 0; ci < 8; ++ci) {
            int cidx = cc*8 + ci;
            #pragma unroll
            for (int kh = 0; kh < 3; ++kh)
                #pragma unroll
                for (int kw = 0; kw < 3; ++kw) {
                    float v0 = s_t[ci][ty+kh][tx+kw];
                    float v1 = s_t[ci][ty+kh][tx+16+kw];
                    float v2 = s_t[ci][ty+16+kh][tx+kw];
                    float v3 = s_t[ci][ty+16+kh][tx+16+kw];
                    float w0 = s_w[cidx*9 + kh*3 + kw];
                    float w1 = s_w[576 + cidx*9 + kh*3 + kw];
                    acc[0][0] += v0*w0; acc[0][1] += v1*w0;
                    acc[0][2] += v2*w0; acc[0][3] += v3*w0;
                    acc[1][0] += v0*w1; acc[1][1] += v1*w1;
                    acc[1][2] += v2*w1; acc[1][3] += v3*w1;
                }
        }
    }

    int oys[4] = {oy0+ty, oy0+ty, oy0+ty+16, oy0+ty+16};
    int oxs[4] = {ox0+tx, ox0+tx+16, ox0+tx, ox0+tx+16};
    #pragma unroll
    for (int c = 0; c < 2; ++c) {
        float bb = b2[c];
        float f0 = wfm[c*3+0], f1 = wfm[c*3+1], f2 = wfm[c*3+2], fb = bfm[c];
        #pragma unroll
        for (int j = 0; j < 4; ++j) {
            int o = ((bz*2 + c)*HW + oys[j])*HW + oxs[j];
            g_ini[o] = acc[c][j] + bb;
            int xb = bz*CIN*HW2 + oys[j]*HW + oxs[j];
            float s = x[xb]*f0 + x[xb + HW2]*f1 + x[xb + 2*HW2]*f2 + fb;
            g_fea[o] = s * 0.25f;
        }
    }
}

// ---------------- trans: relu(M @ v) per patch, via mma.sync ----------------
// CTA: 128 thr (4 warps), tile M=128 patches, N=104 (100 used), K=104 (100 used)
#define TR_STR 108
#define TR_SMEM ((104*TR_STR + 128*TR_STR)*4)
__global__ __launch_bounds__(128) void k_trans() {
    extern __shared__ float smt[];
    float* sBM = smt;                 // 104 x 108 (M matrix, [p][k])
    float* sA  = smt + 104*TR_STR;    // 128 x 108 (patch vectors)
    int tid = threadIdx.x;
    int img = blockIdx.y;
    int l0 = blockIdx.x * 128;
    const float* src = (blockIdx.z == 0) ? g_ini : g_fea;
    float* dst = (blockIdx.z == 0) ? g_UI : g_UF;

    uint32_t* uBM = (uint32_t*)sBM;
    for (int idx = tid; idx < 104*104; idx += 128) {
        int p = idx / 104, k = idx - p*104;
        uBM[p*TR_STR + k] = (p < P2 && k < P2) ? g_M[p*P2 + k] : 0u;
    }
    uint32_t* uA = (uint32_t*)sA;
    const float* sb = src + img*HW2;
    for (int idx = tid; idx < 128*104; idx += 128) {
        int pi = idx / 104, k = idx - pi*104;
        float v = 0.f;
        if (k < P2) {
            int l = l0 + pi;
            int py = k / PS, px = k - py*PS;
            v = sb[((l >> 5)*PS + py)*HW + (l & 31)*PS + px];
        }
        uA[pi*TR_STR + k] = f2tf32(v);
    }
    __syncthreads();

    int wid = tid >> 5, lane = tid & 31;
    int m0 = wid * 32;
    int ac = lane & 3, lq = lane >> 2;

    float d[2][13][4];
    #pragma unroll
    for (int i = 0; i < 2; ++i)
        #pragma unroll
        for (int j = 0; j < 13; ++j)
            #pragma unroll
            for (int q = 0; q < 4; ++q) d[i][j][q] = 0.f;

    #pragma unroll
    for (int kc = 0; kc < 13; ++kc) {
        int k0 = kc*8;
        uint32_t a[2][4], bf[13][2];
        #pragma unroll
        for (int i = 0; i < 2; ++i) {
            const uint32_t* base = uA + (m0 + 16*i + lq)*TR_STR + k0 + ac;
            a[i][0] = base[0];
            a[i][1] = base[8*TR_STR];
            a[i][2] = base[4];
            a[i][3] = base[8*TR_STR + 4];
        }
        #pragma unroll
        for (int j = 0; j < 13; ++j) {
            const uint32_t* base = uBM + (8*j + lq)*TR_STR + k0 + ac;
            bf[j][0] = base[0];
            bf[j][1] = base[4];
        }
        #pragma unroll
        for (int i = 0; i < 2; ++i)
            #pragma unroll
            for (int j = 0; j < 13; ++j)
                mma_tf32(d[i][j], a[i], bf[j]);
    }

    float* db = dst + (size_t)img*NPATCH*P2P;
    #pragma unroll
    for (int i = 0; i < 2; ++i) {
        #pragma unroll
        for (int rr = 0; rr < 2; ++rr) {
            int row = l0 + m0 + 16*i + lq + 8*rr;
            #pragma unroll
            for (int j = 0; j < 13; ++j) {
                int col = 8*j + 2*ac;
                float2 v = make_float2(fmaxf(d[i][j][2*rr + 0], 0.f),
                                       fmaxf(d[i][j][2*rr + 1], 0.f));
                *(float2*)&db[(size_t)row*P2P + col] = v;
            }
        }
    }
}

// ---------------- att: batched 1024x1024x100 NT-GEMM via mma.sync, /100 ----------------
// CTA: 256 thr (8 warps), tile 128x128, K=104
#define AT_STR 108
#define ATT_SMEM (2*128*AT_STR*4)
__global__ __launch_bounds__(256) void k_att(float* __restrict__ out) {
    extern __shared__ float sma[];
    float* sA = sma;                  // 128 x 108 (UI rows)
    float* sB = sma + 128*AT_STR;     // 128 x 108 (UF rows)
    int tid = threadIdx.x;
    int wid = tid >> 5, lane = tid & 31;
    int img = blockIdx.z;
    int gl0 = blockIdx.y*128, gm0 = blockIdx.x*128;
    const float* UI = g_UI + (size_t)img*NPATCH*P2P;
    const float* UF = g_UF + (size_t)img*NPATCH*P2P;

    for (int it = tid; it < 128*26; it += 256) {
        int rr = it/26, k0 = (it - rr*26) << 2;
        float4 va = *(const float4*)&UI[(size_t)(gl0 + rr)*P2P + k0];
        *(uint4*)&sA[rr*AT_STR + k0] =
            make_uint4(f2tf32(va.x), f2tf32(va.y), f2tf32(va.z), f2tf32(va.w));
        float4 vb = *(const float4*)&UF[(size_t)(gm0 + rr)*P2P + k0];
        *(uint4*)&sB[rr*AT_STR + k0] =
            make_uint4(f2tf32(vb.x), f2tf32(vb.y), f2tf32(vb.z), f2tf32(vb.w));
    }
    __syncthreads();

    int m0 = (wid & 3)*32, n0 = (wid >> 2)*64;
    int ac = lane & 3, lq = lane >> 2;
    float d[2][8][4];
    #pragma unroll
    for (int i = 0; i < 2; ++i)
        #pragma unroll
        for (int j = 0; j < 8; ++j)
            #pragma unroll
            for (int q = 0; q < 4; ++q) d[i][j][q] = 0.f;

    const uint32_t* uA = (const uint32_t*)sA;
    const uint32_t* uB = (const uint32_t*)sB;

    #pragma unroll
    for (int kc = 0; kc < 13; ++kc) {
        int k0 = kc*8;
        uint32_t a[2][4], bf[8][2];
        #pragma unroll
        for (int i = 0; i < 2; ++i) {
            const uint32_t* base = uA + (m0 + 16*i + lq)*AT_STR + k0 + ac;
            a[i][0] = base[0];
            a[i][1] = base[8*AT_STR];
            a[i][2] = base[4];
            a[i][3] = base[8*AT_STR + 4];
        }
        #pragma unroll
        for (int j = 0; j < 8; ++j) {
            const uint32_t* base = uB + (n0 + 8*j + lq)*AT_STR + k0 + ac;
            bf[j][0] = base[0];
            bf[j][1] = base[4];
        }
        #pragma unroll
        for (int i = 0; i < 2; ++i)
            #pragma unroll
            for (int j = 0; j < 8; ++j)
                mma_tf32(d[i][j], a[i], bf[j]);
    }

    #pragma unroll
    for (int i = 0; i < 2; ++i) {
        #pragma unroll
        for (int rr = 0; rr < 2; ++rr) {
            int l = gl0 + m0 + 16*i + lq + 8*rr;
            #pragma unroll
            for (int j = 0; j < 8; ++j) {
                int m = gm0 + n0 + 8*j + 2*ac;
                float2 v = make_float2(d[i][j][2*rr + 0]*0.01f, d[i][j][2*rr + 1]*0.01f);
                *(float2*)&out[((long)img*NPATCH + l)*NPATCH + m] = v;
            }
        }
    }
}

extern "C" void kernel_launch(void* const* d_in, const int* in_sizes, int n_in,
                              void* d_out, int out_size) {
    const float* x   = (const float*)d_in[0];
    const float* w1c = (const float*)d_in[1];
    const float* b1c = (const float*)d_in[2];
    const float* w2c = (const float*)d_in[3];
    const float* b2c = (const float*)d_in[4];
    const float* wfm = (const float*)d_in[5];
    const float* bfm = (const float*)d_in[6];
    const float* wl1 = (const float*)d_in[7];
    const float* wl2 = (const float*)d_in[8];
    float* out = (float*)d_out;

    static bool attr_set = false;
    if (!attr_set) {
        cudaFuncSetAttribute(k_trans, cudaFuncAttributeMaxDynamicSharedMemorySize, TR_SMEM);
        cudaFuncSetAttribute(k_att,   cudaFuncAttributeMaxDynamicSharedMemorySize, ATT_SMEM);
        attr_set = true;
    }

    k_buildM<<<P2, 128>>>(wl1, wl2);
    k_conv1<<<dim3(20,40,BATCH), 256>>>(x, w1c, b1c);
    k_conv2_fea<<<dim3(10,10,BATCH), dim3(16,16)>>>(x, w2c, b2c, wfm, bfm);
    k_trans<<<dim3(8, IMGS, 2), 128, TR_SMEM>>>();
    k_att<<<dim3(8,8,IMGS), 256, ATT_SMEM>>>(out);
}

// round 5
// speedup vs baseline: 2.2918x; 1.4594x over previous
#include <cuda_runtime.h>
#include <cuda_fp16.h>
#include <cstdint>

#define BATCH 8
#define CIN 3
#define HW 320
#define HW2 (HW*HW)
#define C1 64
#define PS 10
#define P2 100
#define P2P 104
#define NPATCH 1024
#define IMGS 16

// scratch (device globals — no runtime allocation)
__device__ __half g_t1h[(size_t)BATCH*C1*HW2];   // conv1 out, fp16 (105 MB)
__device__ float g_ini[IMGS*HW2];
__device__ float g_fea[IMGS*HW2];
__device__ uint32_t g_M[P2*P2];                  // (W2@W1) row-major [p][k], tf32 bits
__device__ uint32_t g_wfrag[20*8*32*2];          // conv1 weights, fragment-ordered tf32
__device__ float g_UI[(size_t)IMGS*NPATCH*P2P];
__device__ float g_UF[(size_t)IMGS*NPATCH*P2P];

// ---------------- helpers ----------------
__device__ __forceinline__ uint32_t f2tf32(float f) {
    uint32_t r;
    asm("cvt.rna.tf32.f32 %0, %1;" : "=r"(r) : "f"(f));
    return r;
}
__device__ __forceinline__ void mma_tf32(float* d, const uint32_t* a, const uint32_t* b) {
    asm volatile(
        "mma.sync.aligned.m16n8k8.row.col.f32.tf32.tf32.f32 "
        "{%0,%1,%2,%3}, {%4,%5,%6,%7}, {%8,%9}, {%0,%1,%2,%3};"
        : "+f"(d[0]), "+f"(d[1]), "+f"(d[2]), "+f"(d[3])
        : "r"(a[0]), "r"(a[1]), "r"(a[2]), "r"(a[3]), "r"(b[0]), "r"(b[1]));
}

// ---------------- M = w_lin2 @ w_lin1 (row-major [p][k], tf32 bits) ----------------
__global__ void k_buildM(const float* __restrict__ w1, const float* __restrict__ w2) {
    int p = blockIdx.x;
    int k = threadIdx.x;
    if (k >= P2) return;
    float acc = 0.f;
    for (int q = 0; q < 2*P2; ++q)
        acc += w2[p*2*P2 + q] * w1[q*P2 + k];
    g_M[p*P2 + k] = f2tf32(acc);
}

// ---------------- prepack conv1 weights into fragment order ----------------
// g_wfrag[((kc*4 + jp)*32 + lane)*4 + c]:
//   j = 2*jp + (c>>1), kplus = (c&1)*4, oc = 8j + (lane>>2), k = 8kc + (lane&3) + kplus
__global__ void k_prepw(const float* __restrict__ w) {
    int idx = blockIdx.x*256 + threadIdx.x;   // 10240 total
    int c = idx & 3, lane = (idx >> 2) & 31, jp = (idx >> 7) & 3, kc = idx >> 9;
    int j = 2*jp + (c >> 1);
    int k = 8*kc + (lane & 3) + (c & 1)*4;
    int oc = 8*j + (lane >> 2);
    float v = (k < 147) ? w[oc*147 + k] : 0.f;
    g_wfrag[idx] = f2tf32(v);
}

// ---------------- conv1: 7x7, 3->64, pad 3 via mma.sync tf32 ----------------
// CTA 256 thr, tile 16x16 pixels (M=256), N=64, K=160 (20 chunks of 8)
#define C1_STG 16640          // 64 * 260 floats (stage)
#define C1_INB 1960           // halo tf32 bits + zero pad
#define C1_SMEMB ((C1_STG + C1_INB + 160 + 64)*4)

__global__ __launch_bounds__(256) void k_conv1(const float* __restrict__ x,
                                               const float* __restrict__ b) {
    extern __shared__ uint32_t smw[];
    float*    stg  = (float*)smw;             // 64 x 260
    uint32_t* inb  = smw + C1_STG;            // 1960 (1584 data + 376 zero)
    int*      koff = (int*)(inb + C1_INB);    // 160
    float*    bias = (float*)(koff + 160);    // 64

    int tid = threadIdx.x;
    int img = blockIdx.z;
    int oy0 = blockIdx.y*16, ox0 = blockIdx.x*16;

    if (tid < 160) {
        int k = tid, v = 1584;   // pad k -> zero region
        if (k < 147) { int ci = k/49, r = k - ci*49, kh = r/7, kw = r - kh*7; v = ci*528 + kh*24 + kw; }
        koff[tid] = v;
    }
    if (tid < C1) bias[tid] = b[tid];
    // halo load, tf32 convert
    const float* xb = x + img*CIN*HW2;
    for (int idx = tid; idx < CIN*22*22; idx += 256) {
        int ci = idx / 484; int r = idx - ci*484;
        int iy = r / 22, ix = r - iy*22;
        int gy = oy0 - 3 + iy, gx = ox0 - 3 + ix;
        float v = 0.f;
        if (gy >= 0 && gy < HW && gx >= 0 && gx < HW)
            v = xb[ci*HW2 + gy*HW + gx];
        inb[ci*528 + iy*24 + ix] = f2tf32(v);
    }
    for (int idx = tid; idx < 376; idx += 256) inb[1584 + idx] = 0u;
    __syncthreads();

    int wid = tid >> 5, lane = tid & 31;
    int m0 = wid * 32;
    int ac = lane & 3, lq = lane >> 2;
    int rr0 = m0 + lq;
    int bo0 = ((rr0    ) >> 4)*24 + ((rr0    ) & 15);
    int bo1 = ((rr0 + 8) >> 4)*24 + ((rr0 + 8) & 15);
    int bo2 = ((rr0 +16) >> 4)*24 + ((rr0 +16) & 15);
    int bo3 = ((rr0 +24) >> 4)*24 + ((rr0 +24) & 15);

    float d[2][8][4];
    #pragma unroll
    for (int i = 0; i < 2; ++i)
        #pragma unroll
        for (int j = 0; j < 8; ++j)
            #pragma unroll
            for (int q = 0; q < 4; ++q) d[i][j][q] = 0.f;

    const uint4* wf = (const uint4*)g_wfrag;

    #pragma unroll 4
    for (int kc = 0; kc < 20; ++kc) {
        int k0 = kc*8;
        int ko0 = koff[k0 + ac];
        int ko1 = koff[k0 + ac + 4];
        uint32_t a[2][4];
        a[0][0] = inb[bo0 + ko0];
        a[0][1] = inb[bo1 + ko0];
        a[0][2] = inb[bo0 + ko1];
        a[0][3] = inb[bo1 + ko1];
        a[1][0] = inb[bo2 + ko0];
        a[1][1] = inb[bo3 + ko0];
        a[1][2] = inb[bo2 + ko1];
        a[1][3] = inb[bo3 + ko1];
        uint32_t bf[8][2];
        #pragma unroll
        for (int jp = 0; jp < 4; ++jp) {
            uint4 wv = wf[(kc*4 + jp)*32 + lane];
            bf[2*jp  ][0] = wv.x; bf[2*jp  ][1] = wv.y;
            bf[2*jp+1][0] = wv.z; bf[2*jp+1][1] = wv.w;
        }
        #pragma unroll
        for (int i = 0; i < 2; ++i)
            #pragma unroll
            for (int j = 0; j < 8; ++j)
                mma_tf32(d[i][j], a[i], bf[j]);
    }

    // stage D -> smem [oc][pixel], stride 260 (conflict-free)
    #pragma unroll
    for (int i = 0; i < 2; ++i) {
        #pragma unroll
        for (int rr = 0; rr < 2; ++rr) {
            int pix = m0 + 16*i + 8*rr + lq;
            #pragma unroll
            for (int j = 0; j < 8; ++j) {
                int oc = 8*j + 2*ac;
                stg[oc*260 + pix]     = d[i][j][2*rr + 0];
                stg[(oc+1)*260 + pix] = d[i][j][2*rr + 1];
            }
        }
    }
    __syncthreads();

    // coalesced fp16 store: oc = tid&63, part = tid>>6 (64 pixels each)
    {
        int oc = tid & 63, part = tid >> 6;
        float bb = bias[oc];
        __half* ob = g_t1h + ((size_t)img*C1 + oc)*HW2;
        #pragma unroll
        for (int c2 = 0; c2 < 8; ++c2) {
            int p0 = part*64 + 8*c2;
            float4 v0 = *(const float4*)&stg[oc*260 + p0];
            float4 v1 = *(const float4*)&stg[oc*260 + p0 + 4];
            __half2 h[4];
            h[0] = __floats2half2_rn(v0.x + bb, v0.y + bb);
            h[1] = __floats2half2_rn(v0.z + bb, v0.w + bb);
            h[2] = __floats2half2_rn(v1.x + bb, v1.y + bb);
            h[3] = __floats2half2_rn(v1.z + bb, v1.w + bb);
            int py = p0 >> 4, px = p0 & 15;
            *(uint4*)(ob + (size_t)(oy0 + py)*HW + ox0 + px) = *(uint4*)h;
        }
    }
}

// ---------------- conv2 (3x3, 64->2, pad 1, fp16 in) + fm (1x1, 3->2, /4) ----------------
__global__ __launch_bounds__(256) void k_conv2_fea(const float* __restrict__ x,
        const float* __restrict__ w2, const float* __restrict__ b2,
        const float* __restrict__ wfm, const float* __restrict__ bfm) {
    __shared__ float s_t[8][34][36];
    __shared__ float s_w[2*C1*9];
    int tx = threadIdx.x, ty = threadIdx.y;
    int tid = ty*16 + tx;
    int bz = blockIdx.z;
    int oy0 = blockIdx.y*32, ox0 = blockIdx.x*32;

    for (int idx = tid; idx < 2*C1*9; idx += 256) s_w[idx] = w2[idx];

    float acc[2][4];
    #pragma unroll
    for (int c = 0; c < 2; ++c)
        #pragma unroll
        for (int j = 0; j < 4; ++j) acc[c][j] = 0.f;

    for (int cc = 0; cc < 8; ++cc) {
        __syncthreads();
        for (int idx = tid; idx < 8*34*34; idx += 256) {
            int ci = idx / (34*34); int r = idx % (34*34);
            int iy = r / 34, ix = r % 34;
            int gy = oy0 - 1 + iy, gx = ox0 - 1 + ix;
            float v = 0.f;
            if (gy >= 0 && gy < HW && gx >= 0 && gx < HW)
                v = __half2float(g_t1h[((size_t)(bz*C1 + cc*8 + ci))*HW2 + gy*HW + gx]);
            s_t[ci][iy][ix] = v;
        }
        __syncthreads();
        for (int ci = 0; ci < 8; ++ci) {
            int cidx = cc*8 + ci;
            #pragma unroll
            for (int kh = 0; kh < 3; ++kh)
                #pragma unroll
                for (int kw = 0; kw < 3; ++kw) {
                    float v0 = s_t[ci][ty+kh][tx+kw];
                    float v1 = s_t[ci][ty+kh][tx+16+kw];
                    float v2 = s_t[ci][ty+16+kh][tx+kw];
                    float v3 = s_t[ci][ty+16+kh][tx+16+kw];
                    float w0 = s_w[cidx*9 + kh*3 + kw];
                    float w1 = s_w[576 + cidx*9 + kh*3 + kw];
                    acc[0][0] += v0*w0; acc[0][1] += v1*w0;
                    acc[0][2] += v2*w0; acc[0][3] += v3*w0;
                    acc[1][0] += v0*w1; acc[1][1] += v1*w1;
                    acc[1][2] += v2*w1; acc[1][3] += v3*w1;
                }
        }
    }

    int oys[4] = {oy0+ty, oy0+ty, oy0+ty+16, oy0+ty+16};
    int oxs[4] = {ox0+tx, ox0+tx+16, ox0+tx, ox0+tx+16};
    #pragma unroll
    for (int c = 0; c < 2; ++c) {
        float bb = b2[c];
        float f0 = wfm[c*3+0], f1 = wfm[c*3+1], f2 = wfm[c*3+2], fb = bfm[c];
        #pragma unroll
        for (int j = 0; j < 4; ++j) {
            int o = ((bz*2 + c)*HW + oys[j])*HW + oxs[j];
            g_ini[o] = acc[c][j] + bb;
            int xb = bz*CIN*HW2 + oys[j]*HW + oxs[j];
            float s = x[xb]*f0 + x[xb + HW2]*f1 + x[xb + 2*HW2]*f2 + fb;
            g_fea[o] = s * 0.25f;
        }
    }
}

// ---------------- trans: relu(M @ v) per patch, via mma.sync ----------------
// CTA: 256 thr (8 warps), tile M=128 patches; N split: warps 0-3 j[0,7), 4-7 j[7,13)
#define TR_STR 108
#define TR_SMEM ((104*TR_STR + 128*TR_STR)*4)

template<int J0, int NJ>
__device__ __forceinline__ void trans_warp(const uint32_t* uBM, const uint32_t* uA,
                                           float* db, int m0, int lq, int ac) {
    float d[2][NJ][4];
    #pragma unroll
    for (int i = 0; i < 2; ++i)
        #pragma unroll
        for (int j = 0; j < NJ; ++j)
            #pragma unroll
            for (int q = 0; q < 4; ++q) d[i][j][q] = 0.f;

    #pragma unroll
    for (int kc = 0; kc < 13; ++kc) {
        int k0 = kc*8;
        uint32_t a[2][4], bf[NJ][2];
        #pragma unroll
        for (int i = 0; i < 2; ++i) {
            const uint32_t* base = uA + (m0 + 16*i + lq)*TR_STR + k0 + ac;
            a[i][0] = base[0];
            a[i][1] = base[8*TR_STR];
            a[i][2] = base[4];
            a[i][3] = base[8*TR_STR + 4];
        }
        #pragma unroll
        for (int j = 0; j < NJ; ++j) {
            const uint32_t* base = uBM + (8*(J0 + j) + lq)*TR_STR + k0 + ac;
            bf[j][0] = base[0];
            bf[j][1] = base[4];
        }
        #pragma unroll
        for (int i = 0; i < 2; ++i)
            #pragma unroll
            for (int j = 0; j < NJ; ++j)
                mma_tf32(d[i][j], a[i], bf[j]);
    }

    #pragma unroll
    for (int i = 0; i < 2; ++i) {
        #pragma unroll
        for (int rr = 0; rr < 2; ++rr) {
            int row = m0 + 16*i + lq + 8*rr;
            #pragma unroll
            for (int j = 0; j < NJ; ++j) {
                int col = 8*(J0 + j) + 2*ac;
                float2 v = make_float2(fmaxf(d[i][j][2*rr + 0], 0.f),
                                       fmaxf(d[i][j][2*rr + 1], 0.f));
                *(float2*)&db[(size_t)row*P2P + col] = v;
            }
        }
    }
}

__global__ __launch_bounds__(256) void k_trans() {
    extern __shared__ uint32_t smt[];
    uint32_t* uBM = smt;                  // 104 x 108 (M matrix, [p][k])
    uint32_t* uA  = smt + 104*TR_STR;     // 128 x 108 (patch vectors)
    int tid = threadIdx.x;
    int img = blockIdx.y;
    int l0 = blockIdx.x * 128;
    const float* src = (blockIdx.z == 0) ? g_ini : g_fea;
    float* dst = (blockIdx.z == 0) ? g_UI : g_UF;

    for (int idx = tid; idx < 104*104; idx += 256) {
        int p = idx / 104, k = idx - p*104;
        uBM[p*TR_STR + k] = (p < P2 && k < P2) ? g_M[p*P2 + k] : 0u;
    }
    const float* sb = src + img*HW2;
    for (int idx = tid; idx < 128*104; idx += 256) {
        int pi = idx / 104, k = idx - pi*104;
        float v = 0.f;
        if (k < P2) {
            int l = l0 + pi;
            int py = k / PS, px = k - py*PS;
            v = sb[((l >> 5)*PS + py)*HW + (l & 31)*PS + px];
        }
        uA[pi*TR_STR + k] = f2tf32(v);
    }
    __syncthreads();

    int wid = tid >> 5, lane = tid & 31;
    int m0 = (wid & 3) * 32;
    int ac = lane & 3, lq = lane >> 2;
    float* db = dst + (size_t)img*NPATCH*P2P + (size_t)l0*P2P;
    if (wid < 4) trans_warp<0, 7>(uBM, uA, db, m0, lq, ac);
    else         trans_warp<7, 6>(uBM, uA, db, m0, lq, ac);
}

// ---------------- att: batched 1024x1024x100 NT-GEMM via mma.sync, /100 ----------------
#define AT_STR 108
#define ATT_SMEM (2*128*AT_STR*4)
__global__ __launch_bounds__(256) void k_att(float* __restrict__ out) {
    extern __shared__ float sma[];
    float* sA = sma;                  // 128 x 108 (UI rows)
    float* sB = sma + 128*AT_STR;     // 128 x 108 (UF rows)
    int tid = threadIdx.x;
    int wid = tid >> 5, lane = tid & 31;
    int img = blockIdx.z;
    int gl0 = blockIdx.y*128, gm0 = blockIdx.x*128;
    const float* UI = g_UI + (size_t)img*NPATCH*P2P;
    const float* UF = g_UF + (size_t)img*NPATCH*P2P;

    for (int it = tid; it < 128*26; it += 256) {
        int rr = it/26, k0 = (it - rr*26) << 2;
        float4 va = *(const float4*)&UI[(size_t)(gl0 + rr)*P2P + k0];
        *(uint4*)&sA[rr*AT_STR + k0] =
            make_uint4(f2tf32(va.x), f2tf32(va.y), f2tf32(va.z), f2tf32(va.w));
        float4 vb = *(const float4*)&UF[(size_t)(gm0 + rr)*P2P + k0];
        *(uint4*)&sB[rr*AT_STR + k0] =
            make_uint4(f2tf32(vb.x), f2tf32(vb.y), f2tf32(vb.z), f2tf32(vb.w));
    }
    __syncthreads();

    int m0 = (wid & 3)*32, n0 = (wid >> 2)*64;
    int ac = lane & 3, lq = lane >> 2;
    float d[2][8][4];
    #pragma unroll
    for (int i = 0; i < 2; ++i)
        #pragma unroll
        for (int j = 0; j < 8; ++j)
            #pragma unroll
            for (int q = 0; q < 4; ++q) d[i][j][q] = 0.f;

    const uint32_t* uA = (const uint32_t*)sA;
    const uint32_t* uB = (const uint32_t*)sB;

    #pragma unroll
    for (int kc = 0; kc < 13; ++kc) {
        int k0 = kc*8;
        uint32_t a[2][4], bf[8][2];
        #pragma unroll
        for (int i = 0; i < 2; ++i) {
            const uint32_t* base = uA + (m0 + 16*i + lq)*AT_STR + k0 + ac;
            a[i][0] = base[0];
            a[i][1] = base[8*AT_STR];
            a[i][2] = base[4];
            a[i][3] = base[8*AT_STR + 4];
        }
        #pragma unroll
        for (int j = 0; j < 8; ++j) {
            const uint32_t* base = uB + (n0 + 8*j + lq)*AT_STR + k0 + ac;
            bf[j][0] = base[0];
            bf[j][1] = base[4];
        }
        #pragma unroll
        for (int i = 0; i < 2; ++i)
            #pragma unroll
            for (int j = 0; j < 8; ++j)
                mma_tf32(d[i][j], a[i], bf[j]);
    }

    #pragma unroll
    for (int i = 0; i < 2; ++i) {
        #pragma unroll
        for (int rr = 0; rr < 2; ++rr) {
            int l = gl0 + m0 + 16*i + lq + 8*rr;
            #pragma unroll
            for (int j = 0; j < 8; ++j) {
                int m = gm0 + n0 + 8*j + 2*ac;
                float2 v = make_float2(d[i][j][2*rr + 0]*0.01f, d[i][j][2*rr + 1]*0.01f);
                *(float2*)&out[((long)img*NPATCH + l)*NPATCH + m] = v;
            }
        }
    }
}

extern "C" void kernel_launch(void* const* d_in, const int* in_sizes, int n_in,
                              void* d_out, int out_size) {
    const float* x   = (const float*)d_in[0];
    const float* w1c = (const float*)d_in[1];
    const float* b1c = (const float*)d_in[2];
    const float* w2c = (const float*)d_in[3];
    const float* b2c = (const float*)d_in[4];
    const float* wfm = (const float*)d_in[5];
    const float* bfm = (const float*)d_in[6];
    const float* wl1 = (const float*)d_in[7];
    const float* wl2 = (const float*)d_in[8];
    float* out = (float*)d_out;

    static bool attr_set = false;
    if (!attr_set) {
        cudaFuncSetAttribute(k_conv1, cudaFuncAttributeMaxDynamicSharedMemorySize, C1_SMEMB);
        cudaFuncSetAttribute(k_trans, cudaFuncAttributeMaxDynamicSharedMemorySize, TR_SMEM);
        cudaFuncSetAttribute(k_att,   cudaFuncAttributeMaxDynamicSharedMemorySize, ATT_SMEM);
        attr_set = true;
    }

    k_buildM<<<P2, 128>>>(wl1, wl2);
    k_prepw<<<40, 256>>>(w1c);
    k_conv1<<<dim3(20,20,BATCH), 256, C1_SMEMB>>>(x, b1c);
    k_conv2_fea<<<dim3(10,10,BATCH), dim3(16,16)>>>(x, w2c, b2c, wfm, bfm);
    k_trans<<<dim3(8, IMGS, 2), 256, TR_SMEM>>>();
    k_att<<<dim3(8,8,IMGS), 256, ATT_SMEM>>>(out);
}

// round 6
// speedup vs baseline: 3.5637x; 1.5550x over previous
#include <cuda_runtime.h>
#include <cuda_fp16.h>
#include <cstdint>

#define BATCH 8
#define CIN 3
#define HW 320
#define HW2 (HW*HW)
#define C1 64
#define PS 10
#define P2 100
#define P2P 104
#define NPATCH 1024
#define IMGS 16

// scratch (device globals — no runtime allocation)
__device__ __half g_t1h[(size_t)BATCH*HW2*C1];   // conv1 out, fp16, CHANNEL-LAST [img][pix][ci]
__device__ float g_ini[IMGS*HW2];
__device__ float g_fea[IMGS*HW2];
__device__ uint32_t g_M[P2*P2];                  // (W2@W1) row-major [p][k], tf32 bits
__device__ uint32_t g_wfrag[20*8*32*2];          // conv1 weights, fragment-ordered tf32
__device__ uint32_t g_w2frag[36*64];             // conv2 weights, fragment-ordered fp16x2
__device__ float g_UI[(size_t)IMGS*NPATCH*P2P];
__device__ float g_UF[(size_t)IMGS*NPATCH*P2P];

// ---------------- helpers ----------------
__device__ __forceinline__ uint32_t f2tf32(float f) {
    uint32_t r;
    asm("cvt.rna.tf32.f32 %0, %1;" : "=r"(r) : "f"(f));
    return r;
}
__device__ __forceinline__ void mma_tf32(float* d, const uint32_t* a, const uint32_t* b) {
    asm volatile(
        "mma.sync.aligned.m16n8k8.row.col.f32.tf32.tf32.f32 "
        "{%0,%1,%2,%3}, {%4,%5,%6,%7}, {%8,%9}, {%0,%1,%2,%3};"
        : "+f"(d[0]), "+f"(d[1]), "+f"(d[2]), "+f"(d[3])
        : "r"(a[0]), "r"(a[1]), "r"(a[2]), "r"(a[3]), "r"(b[0]), "r"(b[1]));
}
__device__ __forceinline__ void mma_f16(float* d, const uint32_t* a, const uint32_t* b) {
    asm volatile(
        "mma.sync.aligned.m16n8k16.row.col.f32.f16.f16.f32 "
        "{%0,%1,%2,%3}, {%4,%5,%6,%7}, {%8,%9}, {%0,%1,%2,%3};"
        : "+f"(d[0]), "+f"(d[1]), "+f"(d[2]), "+f"(d[3])
        : "r"(a[0]), "r"(a[1]), "r"(a[2]), "r"(a[3]), "r"(b[0]), "r"(b[1]));
}

// ---------------- M = w_lin2 @ w_lin1 (row-major [p][k], tf32 bits) ----------------
__global__ void k_buildM(const float* __restrict__ w1, const float* __restrict__ w2) {
    int p = blockIdx.x;
    int k = threadIdx.x;
    if (k >= P2) return;
    float acc = 0.f;
    for (int q = 0; q < 2*P2; ++q)
        acc += w2[p*2*P2 + q] * w1[q*P2 + k];
    g_M[p*P2 + k] = f2tf32(acc);
}

// ---------------- prepack conv1 weights into fragment order ----------------
__global__ void k_prepw(const float* __restrict__ w) {
    int idx = blockIdx.x*256 + threadIdx.x;   // 10240 total
    int c = idx & 3, lane = (idx >> 2) & 31, jp = (idx >> 7) & 3, kc = idx >> 9;
    int j = 2*jp + (c >> 1);
    int k = 8*kc + (lane & 3) + (c & 1)*4;
    int oc = 8*j + (lane >> 2);
    float v = (k < 147) ? w[oc*147 + k] : 0.f;
    g_wfrag[idx] = f2tf32(v);
}

// ---------------- prepack conv2 weights (fp16 m16n8k16 B-fragment order) ----------------
// k = tap*64 + ci, tap = kh*3+kw. g_w2frag[kc*64 + lane*2 + r]: halves (klocal=2*(lane&3)+h+8r, n=lane>>2)
__global__ void k_prepw2(const float* __restrict__ w2) {
    int idx = blockIdx.x*256 + threadIdx.x;   // 2304 total
    if (idx >= 36*64) return;
    int r = idx & 1, lane = (idx >> 1) & 31, kc = idx >> 6;
    int n = lane >> 2;
    int tap = kc >> 2, kh = tap/3, kw = tap - kh*3;
    __half h[2];
    #pragma unroll
    for (int hh = 0; hh < 2; ++hh) {
        int kl = (lane & 3)*2 + hh + 8*r;
        int ci = (kc & 3)*16 + kl;
        float v = (n < 2) ? w2[((n*64 + ci)*3 + kh)*3 + kw] : 0.f;
        h[hh] = __float2half_rn(v);
    }
    g_w2frag[idx] = *(uint32_t*)h;
}

// ---------------- conv1: 7x7, 3->64, pad 3 via mma.sync tf32 ----------------
// CTA 256 thr, tile 16x16 pixels (M=256), N=64, K=160; channel-last fp16 output
#define C1_STG 16704          // 64 * 261 floats (stage)
#define C1_INB 1960           // halo tf32 bits + zero pad
#define C1_SMEMB ((C1_STG + C1_INB + 160 + 64)*4)

__global__ __launch_bounds__(256) void k_conv1(const float* __restrict__ x,
                                               const float* __restrict__ b) {
    extern __shared__ uint32_t smw[];
    float*    stg  = (float*)smw;             // 64 x 261
    uint32_t* inb  = smw + C1_STG;            // 1960 (1584 data + 376 zero)
    int*      koff = (int*)(inb + C1_INB);    // 160
    float*    bias = (float*)(koff + 160);    // 64

    int tid = threadIdx.x;
    int img = blockIdx.z;
    int oy0 = blockIdx.y*16, ox0 = blockIdx.x*16;

    if (tid < 160) {
        int k = tid, v = 1584;
        if (k < 147) { int ci = k/49, r = k - ci*49, kh = r/7, kw = r - kh*7; v = ci*528 + kh*24 + kw; }
        koff[tid] = v;
    }
    if (tid < C1) bias[tid] = b[tid];
    const float* xb = x + img*CIN*HW2;
    for (int idx = tid; idx < CIN*22*22; idx += 256) {
        int ci = idx / 484; int r = idx - ci*484;
        int iy = r / 22, ix = r - iy*22;
        int gy = oy0 - 3 + iy, gx = ox0 - 3 + ix;
        float v = 0.f;
        if (gy >= 0 && gy < HW && gx >= 0 && gx < HW)
            v = xb[ci*HW2 + gy*HW + gx];
        inb[ci*528 + iy*24 + ix] = f2tf32(v);
    }
    for (int idx = tid; idx < 376; idx += 256) inb[1584 + idx] = 0u;
    __syncthreads();

    int wid = tid >> 5, lane = tid & 31;
    int m0 = wid * 32;
    int ac = lane & 3, lq = lane >> 2;
    int rr0 = m0 + lq;
    int bo0 = ((rr0    ) >> 4)*24 + ((rr0    ) & 15);
    int bo1 = ((rr0 + 8) >> 4)*24 + ((rr0 + 8) & 15);
    int bo2 = ((rr0 +16) >> 4)*24 + ((rr0 +16) & 15);
    int bo3 = ((rr0 +24) >> 4)*24 + ((rr0 +24) & 15);

    float d[2][8][4];
    #pragma unroll
    for (int i = 0; i < 2; ++i)
        #pragma unroll
        for (int j = 0; j < 8; ++j)
            #pragma unroll
            for (int q = 0; q < 4; ++q) d[i][j][q] = 0.f;

    const uint4* wf = (const uint4*)g_wfrag;

    #pragma unroll 4
    for (int kc = 0; kc < 20; ++kc) {
        int k0 = kc*8;
        int ko0 = koff[k0 + ac];
        int ko1 = koff[k0 + ac + 4];
        uint32_t a[2][4];
        a[0][0] = inb[bo0 + ko0];
        a[0][1] = inb[bo1 + ko0];
        a[0][2] = inb[bo0 + ko1];
        a[0][3] = inb[bo1 + ko1];
        a[1][0] = inb[bo2 + ko0];
        a[1][1] = inb[bo3 + ko0];
        a[1][2] = inb[bo2 + ko1];
        a[1][3] = inb[bo3 + ko1];
        uint32_t bf[8][2];
        #pragma unroll
        for (int jp = 0; jp < 4; ++jp) {
            uint4 wv = wf[(kc*4 + jp)*32 + lane];
            bf[2*jp  ][0] = wv.x; bf[2*jp  ][1] = wv.y;
            bf[2*jp+1][0] = wv.z; bf[2*jp+1][1] = wv.w;
        }
        #pragma unroll
        for (int i = 0; i < 2; ++i)
            #pragma unroll
            for (int j = 0; j < 8; ++j)
                mma_tf32(d[i][j], a[i], bf[j]);
    }

    // stage D -> smem [oc][pixel], stride 261
    #pragma unroll
    for (int i = 0; i < 2; ++i) {
        #pragma unroll
        for (int rr = 0; rr < 2; ++rr) {
            int pix = m0 + 16*i + 8*rr + lq;
            #pragma unroll
            for (int j = 0; j < 8; ++j) {
                int oc = 8*j + 2*ac;
                stg[oc*261 + pix]     = d[i][j][2*rr + 0];
                stg[(oc+1)*261 + pix] = d[i][j][2*rr + 1];
            }
        }
    }
    __syncthreads();

    // channel-last fp16 store: lane -> (pixel group, oc-octet); warp = 4 px x 128B contiguous
    {
        int c = tid & 7;
        int pbase = tid >> 3;     // 0..31
        #pragma unroll
        for (int it = 0; it < 8; ++it) {
            int p = pbase + 32*it;
            uint32_t hh[4];
            #pragma unroll
            for (int q = 0; q < 4; ++q) {
                int oc = 8*c + 2*q;
                float v0 = stg[oc*261 + p]       + bias[oc];
                float v1 = stg[(oc+1)*261 + p]   + bias[oc+1];
                __half2 h = __floats2half2_rn(v0, v1);
                hh[q] = *(uint32_t*)&h;
            }
            int py = p >> 4, px = p & 15;
            size_t gp = (size_t)(oy0 + py)*HW + (ox0 + px);
            *(uint4*)(g_t1h + ((size_t)img*HW2 + gp)*64 + c*8) = *(uint4*)hh;
        }
    }
}

// ---------------- conv2: 3x3, 64->2, pad 1 via fp16 mma.sync ----------------
// CTA 256 thr, tile 8x16 pixels (M=128), N=8 (2 used), K=576 (36 chunks of 16)
__global__ __launch_bounds__(256) void k_conv2(const float* __restrict__ b2) {
    __shared__ __half sH[10*1296];        // halo [hy][hx(stride 72)][ci]
    __shared__ uint32_t sBf[36*64];       // B fragments
    __shared__ float sb2[2];
    int tid = threadIdx.x;
    int img = blockIdx.z;
    int oy0 = blockIdx.y*8, ox0 = blockIdx.x*16;

    if (tid < 2) sb2[tid] = b2[tid];
    for (int i = tid; i < 36*64; i += 256) sBf[i] = g_w2frag[i];
    // halo fill: coalesced 128B/pixel loads
    for (int i = tid; i < 1440; i += 256) {
        int cg = i & 7; int rest = i >> 3;
        int hxp = rest % 18, hy = rest / 18;
        int gy = oy0 - 1 + hy, gx = ox0 - 1 + hxp;
        uint4 v = make_uint4(0,0,0,0);
        if (gy >= 0 && gy < HW && gx >= 0 && gx < HW)
            v = *(const uint4*)(g_t1h + ((size_t)img*HW2 + (size_t)gy*HW + gx)*64 + cg*8);
        *(uint4*)&sH[hy*1296 + hxp*72 + cg*8] = v;
    }
    __syncthreads();

    int wid = tid >> 5, lane = tid & 31;
    int ac = lane & 3, lq = lane >> 2;
    // warp wid -> output row py=wid, pixels px 0..15
    float d[4] = {0.f, 0.f, 0.f, 0.f};

    #pragma unroll
    for (int kc = 0; kc < 36; ++kc) {
        int tap = kc >> 2;
        int kh = tap/3, kw = tap - kh*3;
        int cig = (kc & 3)*16;
        int hy = wid + kh;
        int base = hy*1296 + kw*72 + cig + 2*ac;
        uint32_t a[4];
        a[0] = *(const uint32_t*)&sH[base + lq*72];
        a[1] = *(const uint32_t*)&sH[base + (lq+8)*72];
        a[2] = *(const uint32_t*)&sH[base + lq*72 + 8];
        a[3] = *(const uint32_t*)&sH[base + (lq+8)*72 + 8];
        uint2 bb = *(const uint2*)&sBf[kc*64 + lane*2];
        uint32_t bf[2] = {bb.x, bb.y};
        mma_f16(d, a, bf);
    }

    if (ac == 0) {
        float* o0 = g_ini + ((size_t)img*2 + 0)*HW2;
        float* o1 = g_ini + ((size_t)img*2 + 1)*HW2;
        int gy = oy0 + wid;
        int g0 = gy*HW + ox0 + lq;
        o0[g0]     = d[0] + sb2[0];
        o1[g0]     = d[1] + sb2[1];
        o0[g0 + 8] = d[2] + sb2[0];
        o1[g0 + 8] = d[3] + sb2[1];
    }
}

// ---------------- fea: 1x1 conv 3->2, /4, vectorized ----------------
__global__ __launch_bounds__(256) void k_fea(const float* __restrict__ x,
        const float* __restrict__ wfm, const float* __restrict__ bfm) {
    int idx = blockIdx.x*256 + threadIdx.x;    // over 8*HW2/4
    int img = idx / (HW2/4);
    int p4 = (idx - img*(HW2/4)) * 4;
    const float* xb = x + (size_t)img*CIN*HW2 + p4;
    float4 x0 = *(const float4*)xb;
    float4 x1 = *(const float4*)(xb + HW2);
    float4 x2 = *(const float4*)(xb + 2*HW2);
    #pragma unroll
    for (int c = 0; c < 2; ++c) {
        float f0 = wfm[c*3+0], f1 = wfm[c*3+1], f2 = wfm[c*3+2], fb = bfm[c];
        float4 o;
        o.x = (x0.x*f0 + x1.x*f1 + x2.x*f2 + fb)*0.25f;
        o.y = (x0.y*f0 + x1.y*f1 + x2.y*f2 + fb)*0.25f;
        o.z = (x0.z*f0 + x1.z*f1 + x2.z*f2 + fb)*0.25f;
        o.w = (x0.w*f0 + x1.w*f1 + x2.w*f2 + fb)*0.25f;
        *(float4*)(g_fea + ((size_t)img*2 + c)*HW2 + p4) = o;
    }
}

// ---------------- trans: relu(M @ v) per patch, via mma.sync ----------------
#define TR_STR 108
#define TR_SMEM ((104*TR_STR + 128*TR_STR)*4)

template<int J0, int NJ>
__device__ __forceinline__ void trans_warp(const uint32_t* uBM, const uint32_t* uA,
                                           float* db, int m0, int lq, int ac) {
    float d[2][NJ][4];
    #pragma unroll
    for (int i = 0; i < 2; ++i)
        #pragma unroll
        for (int j = 0; j < NJ; ++j)
            #pragma unroll
            for (int q = 0; q < 4; ++q) d[i][j][q] = 0.f;

    #pragma unroll
    for (int kc = 0; kc < 13; ++kc) {
        int k0 = kc*8;
        uint32_t a[2][4], bf[NJ][2];
        #pragma unroll
        for (int i = 0; i < 2; ++i) {
            const uint32_t* base = uA + (m0 + 16*i + lq)*TR_STR + k0 + ac;
            a[i][0] = base[0];
            a[i][1] = base[8*TR_STR];
            a[i][2] = base[4];
            a[i][3] = base[8*TR_STR + 4];
        }
        #pragma unroll
        for (int j = 0; j < NJ; ++j) {
            const uint32_t* base = uBM + (8*(J0 + j) + lq)*TR_STR + k0 + ac;
            bf[j][0] = base[0];
            bf[j][1] = base[4];
        }
        #pragma unroll
        for (int i = 0; i < 2; ++i)
            #pragma unroll
            for (int j = 0; j < NJ; ++j)
                mma_tf32(d[i][j], a[i], bf[j]);
    }

    #pragma unroll
    for (int i = 0; i < 2; ++i) {
        #pragma unroll
        for (int rr = 0; rr < 2; ++rr) {
            int row = m0 + 16*i + lq + 8*rr;
            #pragma unroll
            for (int j = 0; j < NJ; ++j) {
                int col = 8*(J0 + j) + 2*ac;
                float2 v = make_float2(fmaxf(d[i][j][2*rr + 0], 0.f),
                                       fmaxf(d[i][j][2*rr + 1], 0.f));
                *(float2*)&db[(size_t)row*P2P + col] = v;
            }
        }
    }
}

__global__ __launch_bounds__(256) void k_trans() {
    extern __shared__ uint32_t smt[];
    uint32_t* uBM = smt;
    uint32_t* uA  = smt + 104*TR_STR;
    int tid = threadIdx.x;
    int img = blockIdx.y;
    int l0 = blockIdx.x * 128;
    const float* src = (blockIdx.z == 0) ? g_ini : g_fea;
    float* dst = (blockIdx.z == 0) ? g_UI : g_UF;

    for (int idx = tid; idx < 104*104; idx += 256) {
        int p = idx / 104, k = idx - p*104;
        uBM[p*TR_STR + k] = (p < P2 && k < P2) ? g_M[p*P2 + k] : 0u;
    }
    const float* sb = src + img*HW2;
    for (int idx = tid; idx < 128*104; idx += 256) {
        int pi = idx / 104, k = idx - pi*104;
        float v = 0.f;
        if (k < P2) {
            int l = l0 + pi;
            int py = k / PS, px = k - py*PS;
            v = sb[((l >> 5)*PS + py)*HW + (l & 31)*PS + px];
        }
        uA[pi*TR_STR + k] = f2tf32(v);
    }
    __syncthreads();

    int wid = tid >> 5, lane = tid & 31;
    int m0 = (wid & 3) * 32;
    int ac = lane & 3, lq = lane >> 2;
    float* db = dst + (size_t)img*NPATCH*P2P + (size_t)l0*P2P;
    if (wid < 4) trans_warp<0, 7>(uBM, uA, db, m0, lq, ac);
    else         trans_warp<7, 6>(uBM, uA, db, m0, lq, ac);
}

// ---------------- att: batched 1024x1024x100 NT-GEMM via mma.sync, /100 ----------------
#define AT_STR 108
#define ATT_SMEM (2*128*AT_STR*4)
__global__ __launch_bounds__(256) void k_att(float* __restrict__ out) {
    extern __shared__ float sma[];
    float* sA = sma;
    float* sB = sma + 128*AT_STR;
    int tid = threadIdx.x;
    int wid = tid >> 5, lane = tid & 31;
    int img = blockIdx.z;
    int gl0 = blockIdx.y*128, gm0 = blockIdx.x*128;
    const float* UI = g_UI + (size_t)img*NPATCH*P2P;
    const float* UF = g_UF + (size_t)img*NPATCH*P2P;

    for (int it = tid; it < 128*26; it += 256) {
        int rr = it/26, k0 = (it - rr*26) << 2;
        float4 va = *(const float4*)&UI[(size_t)(gl0 + rr)*P2P + k0];
        *(uint4*)&sA[rr*AT_STR + k0] =
            make_uint4(f2tf32(va.x), f2tf32(va.y), f2tf32(va.z), f2tf32(va.w));
        float4 vb = *(const float4*)&UF[(size_t)(gm0 + rr)*P2P + k0];
        *(uint4*)&sB[rr*AT_STR + k0] =
            make_uint4(f2tf32(vb.x), f2tf32(vb.y), f2tf32(vb.z), f2tf32(vb.w));
    }
    __syncthreads();

    int m0 = (wid & 3)*32, n0 = (wid >> 2)*64;
    int ac = lane & 3, lq = lane >> 2;
    float d[2][8][4];
    #pragma unroll
    for (int i = 0; i < 2; ++i)
        #pragma unroll
        for (int j = 0; j < 8; ++j)
            #pragma unroll
            for (int q = 0; q < 4; ++q) d[i][j][q] = 0.f;

    const uint32_t* uA = (const uint32_t*)sA;
    const uint32_t* uB = (const uint32_t*)sB;

    #pragma unroll
    for (int kc = 0; kc < 13; ++kc) {
        int k0 = kc*8;
        uint32_t a[2][4], bf[8][2];
        #pragma unroll
        for (int i = 0; i < 2; ++i) {
            const uint32_t* base = uA + (m0 + 16*i + lq)*AT_STR + k0 + ac;
            a[i][0] = base[0];
            a[i][1] = base[8*AT_STR];
            a[i][2] = base[4];
            a[i][3] = base[8*AT_STR + 4];
        }
        #pragma unroll
        for (int j = 0; j < 8; ++j) {
            const uint32_t* base = uB + (n0 + 8*j + lq)*AT_STR + k0 + ac;
            bf[j][0] = base[0];
            bf[j][1] = base[4];
        }
        #pragma unroll
        for (int i = 0; i < 2; ++i)
            #pragma unroll
            for (int j = 0; j < 8; ++j)
                mma_tf32(d[i][j], a[i], bf[j]);
    }

    #pragma unroll
    for (int i = 0; i < 2; ++i) {
        #pragma unroll
        for (int rr = 0; rr < 2; ++rr) {
            int l = gl0 + m0 + 16*i + lq + 8*rr;
            #pragma unroll
            for (int j = 0; j < 8; ++j) {
                int m = gm0 + n0 + 8*j + 2*ac;
                float2 v = make_float2(d[i][j][2*rr + 0]*0.01f, d[i][j][2*rr + 1]*0.01f);
                *(float2*)&out[((long)img*NPATCH + l)*NPATCH + m] = v;
            }
        }
    }
}

extern "C" void kernel_launch(void* const* d_in, const int* in_sizes, int n_in,
                              void* d_out, int out_size) {
    const float* x   = (const float*)d_in[0];
    const float* w1c = (const float*)d_in[1];
    const float* b1c = (const float*)d_in[2];
    const float* w2c = (const float*)d_in[3];
    const float* b2c = (const float*)d_in[4];
    const float* wfm = (const float*)d_in[5];
    const float* bfm = (const float*)d_in[6];
    const float* wl1 = (const float*)d_in[7];
    const float* wl2 = (const float*)d_in[8];
    float* out = (float*)d_out;

    static bool attr_set = false;
    if (!attr_set) {
        cudaFuncSetAttribute(k_conv1, cudaFuncAttributeMaxDynamicSharedMemorySize, C1_SMEMB);
        cudaFuncSetAttribute(k_trans, cudaFuncAttributeMaxDynamicSharedMemorySize, TR_SMEM);
        cudaFuncSetAttribute(k_att,   cudaFuncAttributeMaxDynamicSharedMemorySize, ATT_SMEM);
        attr_set = true;
    }

    k_buildM<<<P2, 128>>>(wl1, wl2);
    k_prepw<<<40, 256>>>(w1c);
    k_prepw2<<<9, 256>>>(w2c);
    k_conv1<<<dim3(20,20,BATCH), 256, C1_SMEMB>>>(x, b1c);
    k_conv2<<<dim3(20,40,BATCH), 256>>>(b2c);
    k_fea<<<800, 256>>>(x, wfm, bfm);
    k_trans<<<dim3(8, IMGS, 2), 256, TR_SMEM>>>();
    k_att<<<dim3(8,8,IMGS), 256, ATT_SMEM>>>(out);
}

// round 7
// speedup vs baseline: 3.9485x; 1.1080x over previous
#include <cuda_runtime.h>
#include <cuda_fp16.h>
#include <cstdint>

#define BATCH 8
#define CIN 3
#define HW 320
#define HW2 (HW*HW)
#define C1 64
#define PS 10
#define P2 100
#define P2P 104
#define NPATCH 1024
#define IMGS 16

// scratch (device globals — no runtime allocation)
__device__ __half g_t1h[(size_t)BATCH*HW2*C1];   // conv1 out, fp16, CHANNEL-LAST [img][pix][ci]
__device__ float g_ini[IMGS*HW2];
__device__ float g_fea[IMGS*HW2];
__device__ uint32_t g_M[P2*P2];                  // (W2@W1) row-major [p][k], tf32 bits
__device__ uint32_t g_wfrag[12*4*32*4];          // conv1 weights, fp16 fragment order (K'=192)
__device__ uint32_t g_w2frag[36*64];             // conv2 weights, fragment-ordered fp16x2
__device__ float g_UI[(size_t)IMGS*NPATCH*P2P];
__device__ float g_UF[(size_t)IMGS*NPATCH*P2P];

// ---------------- helpers ----------------
__device__ __forceinline__ uint32_t f2tf32(float f) {
    uint32_t r;
    asm("cvt.rna.tf32.f32 %0, %1;" : "=r"(r) : "f"(f));
    return r;
}
__device__ __forceinline__ void mma_tf32(float* d, const uint32_t* a, const uint32_t* b) {
    asm volatile(
        "mma.sync.aligned.m16n8k8.row.col.f32.tf32.tf32.f32 "
        "{%0,%1,%2,%3}, {%4,%5,%6,%7}, {%8,%9}, {%0,%1,%2,%3};"
        : "+f"(d[0]), "+f"(d[1]), "+f"(d[2]), "+f"(d[3])
        : "r"(a[0]), "r"(a[1]), "r"(a[2]), "r"(a[3]), "r"(b[0]), "r"(b[1]));
}
__device__ __forceinline__ void mma_f16(float* d, const uint32_t* a, const uint32_t* b) {
    asm volatile(
        "mma.sync.aligned.m16n8k16.row.col.f32.f16.f16.f32 "
        "{%0,%1,%2,%3}, {%4,%5,%6,%7}, {%8,%9}, {%0,%1,%2,%3};"
        : "+f"(d[0]), "+f"(d[1]), "+f"(d[2]), "+f"(d[3])
        : "r"(a[0]), "r"(a[1]), "r"(a[2]), "r"(a[3]), "r"(b[0]), "r"(b[1]));
}

// ---------------- M = w_lin2 @ w_lin1 (row-major [p][k], tf32 bits) ----------------
__global__ void k_buildM(const float* __restrict__ w1, const float* __restrict__ w2) {
    int p = blockIdx.x;
    int k = threadIdx.x;
    if (k >= P2) return;
    float acc = 0.f;
    for (int q = 0; q < 2*P2; ++q)
        acc += w2[p*2*P2 + q] * w1[q*P2 + k];
    g_M[p*P2 + k] = f2tf32(acc);
}

// ---------------- prepack conv1 weights: fp16 m16n8k16 B-fragments, K'=192 ----------------
// K' = ci*64 + kh*8 + kw (kh,kw in 0..7; kh==7 or kw==7 -> zero weight)
__global__ void k_prepw(const float* __restrict__ w) {
    int idx = blockIdx.x*256 + threadIdx.x;   // 6144 total
    int c = idx & 3, lane = (idx >> 2) & 31, jp = (idx >> 7) & 3, kc = idx >> 9;
    int j = 2*jp + (c >> 1), r = c & 1;
    int oc = 8*j + (lane >> 2);
    __half h2[2];
    #pragma unroll
    for (int hh = 0; hh < 2; ++hh) {
        int k = 16*kc + 2*(lane & 3) + 8*r + hh;
        int ci = k >> 6, kh = (k >> 3) & 7, kw = k & 7;
        float v = (kh < 7 && kw < 7) ? w[oc*147 + ci*49 + kh*7 + kw] : 0.f;
        h2[hh] = __float2half_rn(v);
    }
    g_wfrag[idx] = *(uint32_t*)h2;
}

// ---------------- prepack conv2 weights (fp16 m16n8k16 B-fragment order) ----------------
__global__ void k_prepw2(const float* __restrict__ w2) {
    int idx = blockIdx.x*256 + threadIdx.x;   // 2304 total
    if (idx >= 36*64) return;
    int r = idx & 1, lane = (idx >> 1) & 31, kc = idx >> 6;
    int n = lane >> 2;
    int tap = kc >> 2, kh = tap/3, kw = tap - kh*3;
    __half h[2];
    #pragma unroll
    for (int hh = 0; hh < 2; ++hh) {
        int kl = (lane & 3)*2 + hh + 8*r;
        int ci = (kc & 3)*16 + kl;
        float v = (n < 2) ? w2[((n*64 + ci)*3 + kh)*3 + kw] : 0.f;
        h[hh] = __float2half_rn(v);
    }
    g_w2frag[idx] = *(uint32_t*)h;
}

// ---------------- conv1: 7x7, 3->64, pad 3 via fp16 mma.sync ----------------
// CTA 256 thr, tile 16x16 pixels (M=256), N=64, K'=192 (12 chunks of 16)
#define C1_STG 16704          // 64 * 261 floats (stage)
#define C1_HP  1984           // shifted-pair halo (__half2)
#define C1_H   996            // raw halo (__half), 1992 halves
#define C1_SMEMB ((C1_STG + C1_HP + C1_H + 64)*4)

__global__ __launch_bounds__(256) void k_conv1(const float* __restrict__ x,
                                               const float* __restrict__ b) {
    extern __shared__ uint32_t smw[];
    float*    stg  = (float*)smw;             // 64 x 261
    uint32_t* hp   = smw + C1_STG;            // 1984 pairs
    __half*   h    = (__half*)(smw + C1_STG + C1_HP);   // 1992 halves
    float*    bias = (float*)(smw + C1_STG + C1_HP + C1_H);  // 64

    int tid = threadIdx.x;
    int img = blockIdx.z;
    int oy0 = blockIdx.y*16, ox0 = blockIdx.x*16;

    if (tid < C1) bias[tid] = b[tid];
    // halo fill (fp16): 3 ci x 22 rows x stride 24 (cols 22,23 + tail zeroed)
    const float* xb = x + img*CIN*HW2;
    for (int idx = tid; idx < 1992; idx += 256) {
        float v = 0.f;
        if (idx < 1584) {
            int ci = idx / 528; int r = idx - ci*528;
            int iy = r / 24, ix = r - iy*24;
            int gy = oy0 - 3 + iy, gx = ox0 - 3 + ix;
            if (ix < 22 && gy >= 0 && gy < HW && gx >= 0 && gx < HW)
                v = xb[ci*HW2 + gy*HW + gx];
        }
        h[idx] = __float2half_rn(v);
    }
    __syncthreads();
    // shifted-pair build: hp[i] = (h[i], h[i+1])
    for (int idx = tid; idx < C1_HP; idx += 256) {
        __half2 p = __halves2half2(h[idx], h[idx+1]);
        hp[idx] = *(uint32_t*)&p;
    }
    __syncthreads();

    int wid = tid >> 5, lane = tid & 31;
    int m0 = wid * 32;
    int ac = lane & 3, lq = lane >> 2;
    int rr0 = m0 + lq;
    int bo0 = ((rr0    ) >> 4)*24 + ((rr0    ) & 15);
    int bo1 = ((rr0 + 8) >> 4)*24 + ((rr0 + 8) & 15);
    int bo2 = ((rr0 +16) >> 4)*24 + ((rr0 +16) & 15);
    int bo3 = ((rr0 +24) >> 4)*24 + ((rr0 +24) & 15);

    float d[2][8][4];
    #pragma unroll
    for (int i = 0; i < 2; ++i)
        #pragma unroll
        for (int j = 0; j < 8; ++j)
            #pragma unroll
            for (int q = 0; q < 4; ++q) d[i][j][q] = 0.f;

    const uint4* wf = (const uint4*)g_wfrag;

    #pragma unroll 4
    for (int kc = 0; kc < 12; ++kc) {
        int klo = (kc >> 2)*528 + (kc & 3)*48 + 2*ac;
        int khi = klo + 24;
        uint32_t a[2][4];
        a[0][0] = hp[bo0 + klo];
        a[0][1] = hp[bo1 + klo];
        a[0][2] = hp[bo0 + khi];
        a[0][3] = hp[bo1 + khi];
        a[1][0] = hp[bo2 + klo];
        a[1][1] = hp[bo3 + klo];
        a[1][2] = hp[bo2 + khi];
        a[1][3] = hp[bo3 + khi];
        uint32_t bf[8][2];
        #pragma unroll
        for (int jp = 0; jp < 4; ++jp) {
            uint4 wv = wf[(kc*4 + jp)*32 + lane];
            bf[2*jp  ][0] = wv.x; bf[2*jp  ][1] = wv.y;
            bf[2*jp+1][0] = wv.z; bf[2*jp+1][1] = wv.w;
        }
        #pragma unroll
        for (int i = 0; i < 2; ++i)
            #pragma unroll
            for (int j = 0; j < 8; ++j)
                mma_f16(d[i][j], a[i], bf[j]);
    }

    // stage D -> smem [oc][pixel], stride 261
    __syncthreads();
    #pragma unroll
    for (int i = 0; i < 2; ++i) {
        #pragma unroll
        for (int rr = 0; rr < 2; ++rr) {
            int pix = m0 + 16*i + 8*rr + lq;
            #pragma unroll
            for (int j = 0; j < 8; ++j) {
                int oc = 8*j + 2*ac;
                stg[oc*261 + pix]     = d[i][j][2*rr + 0];
                stg[(oc+1)*261 + pix] = d[i][j][2*rr + 1];
            }
        }
    }
    __syncthreads();

    // channel-last fp16 store
    {
        int c = tid & 7;
        int pbase = tid >> 3;
        #pragma unroll
        for (int it = 0; it < 8; ++it) {
            int p = pbase + 32*it;
            uint32_t hh[4];
            #pragma unroll
            for (int q = 0; q < 4; ++q) {
                int oc = 8*c + 2*q;
                float v0 = stg[oc*261 + p]     + bias[oc];
                float v1 = stg[(oc+1)*261 + p] + bias[oc+1];
                __half2 hv = __floats2half2_rn(v0, v1);
                hh[q] = *(uint32_t*)&hv;
            }
            int py = p >> 4, px = p & 15;
            size_t gp = (size_t)(oy0 + py)*HW + (ox0 + px);
            *(uint4*)(g_t1h + ((size_t)img*HW2 + gp)*64 + c*8) = *(uint4*)hh;
        }
    }
}

// ---------------- conv2: 3x3, 64->2, pad 1 via fp16 mma.sync ----------------
__global__ __launch_bounds__(256) void k_conv2(const float* __restrict__ b2) {
    __shared__ __half sH[10*1296];        // halo [hy][hx(stride 72)][ci]
    __shared__ uint32_t sBf[36*64];       // B fragments
    __shared__ float sb2[2];
    int tid = threadIdx.x;
    int img = blockIdx.z;
    int oy0 = blockIdx.y*8, ox0 = blockIdx.x*16;

    if (tid < 2) sb2[tid] = b2[tid];
    for (int i = tid; i < 36*64; i += 256) sBf[i] = g_w2frag[i];
    for (int i = tid; i < 1440; i += 256) {
        int cg = i & 7; int rest = i >> 3;
        int hxp = rest % 18, hy = rest / 18;
        int gy = oy0 - 1 + hy, gx = ox0 - 1 + hxp;
        uint4 v = make_uint4(0,0,0,0);
        if (gy >= 0 && gy < HW && gx >= 0 && gx < HW)
            v = *(const uint4*)(g_t1h + ((size_t)img*HW2 + (size_t)gy*HW + gx)*64 + cg*8);
        *(uint4*)&sH[hy*1296 + hxp*72 + cg*8] = v;
    }
    __syncthreads();

    int wid = tid >> 5, lane = tid & 31;
    int ac = lane & 3, lq = lane >> 2;
    float d[4] = {0.f, 0.f, 0.f, 0.f};

    #pragma unroll
    for (int kc = 0; kc < 36; ++kc) {
        int tap = kc >> 2;
        int kh = tap/3, kw = tap - kh*3;
        int cig = (kc & 3)*16;
        int hy = wid + kh;
        int base = hy*1296 + kw*72 + cig + 2*ac;
        uint32_t a[4];
        a[0] = *(const uint32_t*)&sH[base + lq*72];
        a[1] = *(const uint32_t*)&sH[base + (lq+8)*72];
        a[2] = *(const uint32_t*)&sH[base + lq*72 + 8];
        a[3] = *(const uint32_t*)&sH[base + (lq+8)*72 + 8];
        uint2 bb = *(const uint2*)&sBf[kc*64 + lane*2];
        uint32_t bf[2] = {bb.x, bb.y};
        mma_f16(d, a, bf);
    }

    if (ac == 0) {
        float* o0 = g_ini + ((size_t)img*2 + 0)*HW2;
        float* o1 = g_ini + ((size_t)img*2 + 1)*HW2;
        int gy = oy0 + wid;
        int g0 = gy*HW + ox0 + lq;
        o0[g0]     = d[0] + sb2[0];
        o1[g0]     = d[1] + sb2[1];
        o0[g0 + 8] = d[2] + sb2[0];
        o1[g0 + 8] = d[3] + sb2[1];
    }
}

// ---------------- fea: 1x1 conv 3->2, /4, vectorized ----------------
__global__ __launch_bounds__(256) void k_fea(const float* __restrict__ x,
        const float* __restrict__ wfm, const float* __restrict__ bfm) {
    int idx = blockIdx.x*256 + threadIdx.x;
    int img = idx / (HW2/4);
    int p4 = (idx - img*(HW2/4)) * 4;
    const float* xb = x + (size_t)img*CIN*HW2 + p4;
    float4 x0 = *(const float4*)xb;
    float4 x1 = *(const float4*)(xb + HW2);
    float4 x2 = *(const float4*)(xb + 2*HW2);
    #pragma unroll
    for (int c = 0; c < 2; ++c) {
        float f0 = wfm[c*3+0], f1 = wfm[c*3+1], f2 = wfm[c*3+2], fb = bfm[c];
        float4 o;
        o.x = (x0.x*f0 + x1.x*f1 + x2.x*f2 + fb)*0.25f;
        o.y = (x0.y*f0 + x1.y*f1 + x2.y*f2 + fb)*0.25f;
        o.z = (x0.z*f0 + x1.z*f1 + x2.z*f2 + fb)*0.25f;
        o.w = (x0.w*f0 + x1.w*f1 + x2.w*f2 + fb)*0.25f;
        *(float4*)(g_fea + ((size_t)img*2 + c)*HW2 + p4) = o;
    }
}

// ---------------- trans: relu(M @ v) per patch, via mma.sync ----------------
#define TR_STR 108
#define TR_SMEM ((104*TR_STR + 128*TR_STR)*4)

template<int J0, int NJ>
__device__ __forceinline__ void trans_warp(const uint32_t* uBM, const uint32_t* uA,
                                           float* db, int m0, int lq, int ac) {
    float d[2][NJ][4];
    #pragma unroll
    for (int i = 0; i < 2; ++i)
        #pragma unroll
        for (int j = 0; j < NJ; ++j)
            #pragma unroll
            for (int q = 0; q < 4; ++q) d[i][j][q] = 0.f;

    #pragma unroll
    for (int kc = 0; kc < 13; ++kc) {
        int k0 = kc*8;
        uint32_t a[2][4], bf[NJ][2];
        #pragma unroll
        for (int i = 0; i < 2; ++i) {
            const uint32_t* base = uA + (m0 + 16*i + lq)*TR_STR + k0 + ac;
            a[i][0] = base[0];
            a[i][1] = base[8*TR_STR];
            a[i][2] = base[4];
            a[i][3] = base[8*TR_STR + 4];
        }
        #pragma unroll
        for (int j = 0; j < NJ; ++j) {
            const uint32_t* base = uBM + (8*(J0 + j) + lq)*TR_STR + k0 + ac;
            bf[j][0] = base[0];
            bf[j][1] = base[4];
        }
        #pragma unroll
        for (int i = 0; i < 2; ++i)
            #pragma unroll
            for (int j = 0; j < NJ; ++j)
                mma_tf32(d[i][j], a[i], bf[j]);
    }

    #pragma unroll
    for (int i = 0; i < 2; ++i) {
        #pragma unroll
        for (int rr = 0; rr < 2; ++rr) {
            int row = m0 + 16*i + lq + 8*rr;
            #pragma unroll
            for (int j = 0; j < NJ; ++j) {
                int col = 8*(J0 + j) + 2*ac;
                float2 v = make_float2(fmaxf(d[i][j][2*rr + 0], 0.f),
                                       fmaxf(d[i][j][2*rr + 1], 0.f));
                *(float2*)&db[(size_t)row*P2P + col] = v;
            }
        }
    }
}

__global__ __launch_bounds__(256) void k_trans() {
    extern __shared__ uint32_t smt[];
    uint32_t* uBM = smt;
    uint32_t* uA  = smt + 104*TR_STR;
    int tid = threadIdx.x;
    int img = blockIdx.y;
    int l0 = blockIdx.x * 128;
    const float* src = (blockIdx.z == 0) ? g_ini : g_fea;
    float* dst = (blockIdx.z == 0) ? g_UI : g_UF;

    for (int idx = tid; idx < 104*104; idx += 256) {
        int p = idx / 104, k = idx - p*104;
        uBM[p*TR_STR + k] = (p < P2 && k < P2) ? g_M[p*P2 + k] : 0u;
    }
    const float* sb = src + img*HW2;
    for (int idx = tid; idx < 128*104; idx += 256) {
        int pi = idx / 104, k = idx - pi*104;
        float v = 0.f;
        if (k < P2) {
            int l = l0 + pi;
            int py = k / PS, px = k - py*PS;
            v = sb[((l >> 5)*PS + py)*HW + (l & 31)*PS + px];
        }
        uA[pi*TR_STR + k] = f2tf32(v);
    }
    __syncthreads();

    int wid = tid >> 5, lane = tid & 31;
    int m0 = (wid & 3) * 32;
    int ac = lane & 3, lq = lane >> 2;
    float* db = dst + (size_t)img*NPATCH*P2P + (size_t)l0*P2P;
    if (wid < 4) trans_warp<0, 7>(uBM, uA, db, m0, lq, ac);
    else         trans_warp<7, 6>(uBM, uA, db, m0, lq, ac);
}

// ---------------- att: batched 1024x1024x100 NT-GEMM via mma.sync, /100 ----------------
#define AT_STR 108
#define ATT_SMEM (2*128*AT_STR*4)
__global__ __launch_bounds__(256) void k_att(float* __restrict__ out) {
    extern __shared__ float sma[];
    float* sA = sma;
    float* sB = sma + 128*AT_STR;
    int tid = threadIdx.x;
    int wid = tid >> 5, lane = tid & 31;
    int img = blockIdx.z;
    int gl0 = blockIdx.y*128, gm0 = blockIdx.x*128;
    const float* UI = g_UI + (size_t)img*NPATCH*P2P;
    const float* UF = g_UF + (size_t)img*NPATCH*P2P;

    for (int it = tid; it < 128*26; it += 256) {
        int rr = it/26, k0 = (it - rr*26) << 2;
        float4 va = *(const float4*)&UI[(size_t)(gl0 + rr)*P2P + k0];
        *(uint4*)&sA[rr*AT_STR + k0] =
            make_uint4(f2tf32(va.x), f2tf32(va.y), f2tf32(va.z), f2tf32(va.w));
        float4 vb = *(const float4*)&UF[(size_t)(gm0 + rr)*P2P + k0];
        *(uint4*)&sB[rr*AT_STR + k0] =
            make_uint4(f2tf32(vb.x), f2tf32(vb.y), f2tf32(vb.z), f2tf32(vb.w));
    }
    __syncthreads();

    int m0 = (wid & 3)*32, n0 = (wid >> 2)*64;
    int ac = lane & 3, lq = lane >> 2;
    float d[2][8][4];
    #pragma unroll
    for (int i = 0; i < 2; ++i)
        #pragma unroll
        for (int j = 0; j < 8; ++j)
            #pragma unroll
            for (int q = 0; q < 4; ++q) d[i][j][q] = 0.f;

    const uint32_t* uA = (const uint32_t*)sA;
    const uint32_t* uB = (const uint32_t*)sB;

    #pragma unroll
    for (int kc = 0; kc < 13; ++kc) {
        int k0 = kc*8;
        uint32_t a[2][4], bf[8][2];
        #pragma unroll
        for (int i = 0; i < 2; ++i) {
            const uint32_t* base = uA + (m0 + 16*i + lq)*AT_STR + k0 + ac;
            a[i][0] = base[0];
            a[i][1] = base[8*AT_STR];
            a[i][2] = base[4];
            a[i][3] = base[8*AT_STR + 4];
        }
        #pragma unroll
        for (int j = 0; j < 8; ++j) {
            const uint32_t* base = uB + (n0 + 8*j + lq)*AT_STR + k0 + ac;
            bf[j][0] = base[0];
            bf[j][1] = base[4];
        }
        #pragma unroll
        for (int i = 0; i < 2; ++i)
            #pragma unroll
            for (int j = 0; j < 8; ++j)
                mma_tf32(d[i][j], a[i], bf[j]);
    }

    #pragma unroll
    for (int i = 0; i < 2; ++i) {
        #pragma unroll
        for (int rr = 0; rr < 2; ++rr) {
            int l = gl0 + m0 + 16*i + lq + 8*rr;
            #pragma unroll
            for (int j = 0; j < 8; ++j) {
                int m = gm0 + n0 + 8*j + 2*ac;
                float2 v = make_float2(d[i][j][2*rr + 0]*0.01f, d[i][j][2*rr + 1]*0.01f);
                *(float2*)&out[((long)img*NPATCH + l)*NPATCH + m] = v;
            }
        }
    }
}

extern "C" void kernel_launch(void* const* d_in, const int* in_sizes, int n_in,
                              void* d_out, int out_size) {
    const float* x   = (const float*)d_in[0];
    const float* w1c = (const float*)d_in[1];
    const float* b1c = (const float*)d_in[2];
    const float* w2c = (const float*)d_in[3];
    const float* b2c = (const float*)d_in[4];
    const float* wfm = (const float*)d_in[5];
    const float* bfm = (const float*)d_in[6];
    const float* wl1 = (const float*)d_in[7];
    const float* wl2 = (const float*)d_in[8];
    float* out = (float*)d_out;

    static bool attr_set = false;
    if (!attr_set) {
        cudaFuncSetAttribute(k_conv1, cudaFuncAttributeMaxDynamicSharedMemorySize, C1_SMEMB);
        cudaFuncSetAttribute(k_trans, cudaFuncAttributeMaxDynamicSharedMemorySize, TR_SMEM);
        cudaFuncSetAttribute(k_att,   cudaFuncAttributeMaxDynamicSharedMemorySize, ATT_SMEM);
        attr_set = true;
    }

    k_buildM<<<P2, 128>>>(wl1, wl2);
    k_prepw<<<24, 256>>>(w1c);
    k_prepw2<<<9, 256>>>(w2c);
    k_conv1<<<dim3(20,20,BATCH), 256, C1_SMEMB>>>(x, b1c);
    k_conv2<<<dim3(20,40,BATCH), 256>>>(b2c);
    k_fea<<<800, 256>>>(x, wfm, bfm);
    k_trans<<<dim3(8, IMGS, 2), 256, TR_SMEM>>>();
    k_att<<<dim3(8,8,IMGS), 256, ATT_SMEM>>>(out);
}

// round 8
// speedup vs baseline: 3.9499x; 1.0004x over previous
#include <cuda_runtime.h>
#include <cuda_fp16.h>
#include <cstdint>

#define BATCH 8
#define CIN 3
#define HW 320
#define HW2 (HW*HW)
#define C1 64
#define PS 10
#define P2 100
#define P2P 104
#define NPATCH 1024
#define IMGS 16

// scratch (device globals — no runtime allocation)
__device__ __half g_t1h[(size_t)BATCH*HW2*C1];   // conv1 out, fp16, CHANNEL-LAST [img][pix][ci]
__device__ float g_ini[IMGS*HW2];
__device__ float g_fea[IMGS*HW2];
__device__ uint32_t g_M[P2*P2];                  // (W2@W1) row-major [p][k], tf32 bits
__device__ uint32_t g_wfrag[12*4*32*4];          // conv1 weights, fp16 fragment order (K'=192)
__device__ uint32_t g_w2frag[36*64];             // conv2 weights, fragment-ordered fp16x2
__device__ float g_UI[(size_t)IMGS*NPATCH*P2P];
__device__ float g_UF[(size_t)IMGS*NPATCH*P2P];

// ---------------- helpers ----------------
__device__ __forceinline__ uint32_t f2tf32(float f) {
    uint32_t r;
    asm("cvt.rna.tf32.f32 %0, %1;" : "=r"(r) : "f"(f));
    return r;
}
__device__ __forceinline__ void mma_tf32(float* d, const uint32_t* a, const uint32_t* b) {
    asm volatile(
        "mma.sync.aligned.m16n8k8.row.col.f32.tf32.tf32.f32 "
        "{%0,%1,%2,%3}, {%4,%5,%6,%7}, {%8,%9}, {%0,%1,%2,%3};"
        : "+f"(d[0]), "+f"(d[1]), "+f"(d[2]), "+f"(d[3])
        : "r"(a[0]), "r"(a[1]), "r"(a[2]), "r"(a[3]), "r"(b[0]), "r"(b[1]));
}
__device__ __forceinline__ void mma_f16(float* d, const uint32_t* a, const uint32_t* b) {
    asm volatile(
        "mma.sync.aligned.m16n8k16.row.col.f32.f16.f16.f32 "
        "{%0,%1,%2,%3}, {%4,%5,%6,%7}, {%8,%9}, {%0,%1,%2,%3};"
        : "+f"(d[0]), "+f"(d[1]), "+f"(d[2]), "+f"(d[3])
        : "r"(a[0]), "r"(a[1]), "r"(a[2]), "r"(a[3]), "r"(b[0]), "r"(b[1]));
}
__device__ __forceinline__ void cp_async4(uint32_t saddr, const void* gptr, uint32_t src_sz) {
    asm volatile("cp.async.ca.shared.global [%0], [%1], 4, %2;"
                 :: "r"(saddr), "l"(gptr), "r"(src_sz));
}

// ---------------- M = w_lin2 @ w_lin1 (row-major [p][k], tf32 bits) ----------------
__global__ void k_buildM(const float* __restrict__ w1, const float* __restrict__ w2) {
    int p = blockIdx.x;
    int k = threadIdx.x;
    if (k >= P2) return;
    float acc = 0.f;
    for (int q = 0; q < 2*P2; ++q)
        acc += w2[p*2*P2 + q] * w1[q*P2 + k];
    g_M[p*P2 + k] = f2tf32(acc);
}

// ---------------- prepack conv1 weights: fp16 m16n8k16 B-fragments, K'=192 ----------------
__global__ void k_prepw(const float* __restrict__ w) {
    int idx = blockIdx.x*256 + threadIdx.x;   // 6144 total
    int c = idx & 3, lane = (idx >> 2) & 31, jp = (idx >> 7) & 3, kc = idx >> 9;
    int j = 2*jp + (c >> 1), r = c & 1;
    int oc = 8*j + (lane >> 2);
    __half h2[2];
    #pragma unroll
    for (int hh = 0; hh < 2; ++hh) {
        int k = 16*kc + 2*(lane & 3) + 8*r + hh;
        int ci = k >> 6, kh = (k >> 3) & 7, kw = k & 7;
        float v = (kh < 7 && kw < 7) ? w[oc*147 + ci*49 + kh*7 + kw] : 0.f;
        h2[hh] = __float2half_rn(v);
    }
    g_wfrag[idx] = *(uint32_t*)h2;
}

// ---------------- prepack conv2 weights (fp16 m16n8k16 B-fragment order) ----------------
__global__ void k_prepw2(const float* __restrict__ w2) {
    int idx = blockIdx.x*256 + threadIdx.x;   // 2304 total
    if (idx >= 36*64) return;
    int r = idx & 1, lane = (idx >> 1) & 31, kc = idx >> 6;
    int n = lane >> 2;
    int tap = kc >> 2, kh = tap/3, kw = tap - kh*3;
    __half h[2];
    #pragma unroll
    for (int hh = 0; hh < 2; ++hh) {
        int kl = (lane & 3)*2 + hh + 8*r;
        int ci = (kc & 3)*16 + kl;
        float v = (n < 2) ? w2[((n*64 + ci)*3 + kh)*3 + kw] : 0.f;
        h[hh] = __float2half_rn(v);
    }
    g_w2frag[idx] = *(uint32_t*)h;
}

// ---------------- conv1: 7x7, 3->64, pad 3 via fp16 mma.sync, cp.async pipelined ----------------
// CTA 256 thr, 4 tiles of 16x16 pixels along x; K'=192 (12 chunks of 16)
#define C1_TPC 4
#define OFS_STG 0            // 64 x 261 floats
#define OFS_HP  16704        // 1984 pairs
#define OFS_HB  18688        // 2 x 1992 fp32 halo
#define OFS_BIAS 22672       // 64
#define C1_SMEMB (22736*4)

__global__ __launch_bounds__(256) void k_conv1(const float* __restrict__ x,
                                               const float* __restrict__ b) {
    extern __shared__ uint32_t smw[];
    float*    stg  = (float*)(smw + OFS_STG);
    uint32_t* hp   = smw + OFS_HP;
    float*    hbuf = (float*)(smw + OFS_HB);
    float*    bias = (float*)(smw + OFS_BIAS);

    int tid = threadIdx.x;
    int img = blockIdx.z;
    int oy0 = blockIdx.y*16;
    int oxbase = blockIdx.x*(16*C1_TPC);
    const float* xb = x + img*CIN*HW2;

    if (tid < C1) bias[tid] = b[tid];

    int wid = tid >> 5, lane = tid & 31;
    int m0 = wid * 32;
    int ac = lane & 3, lq = lane >> 2;
    int rr0 = m0 + lq;
    int bo0 = ((rr0    ) >> 4)*24 + ((rr0    ) & 15);
    int bo1 = ((rr0 + 8) >> 4)*24 + ((rr0 + 8) & 15);
    int bo2 = ((rr0 +16) >> 4)*24 + ((rr0 +16) & 15);
    int bo3 = ((rr0 +24) >> 4)*24 + ((rr0 +24) & 15);
    const uint4* wf = (const uint4*)g_wfrag;

    // issue halo cp.async for tile t into buffer buf
    auto issue_halo = [&](int t, int buf) {
        int ox0 = oxbase + t*16;
        float* hb = hbuf + buf*1992;
        for (int idx = tid; idx < 1992; idx += 256) {
            uint32_t saddr = (uint32_t)__cvta_generic_to_shared(hb + idx);
            const float* gp = xb;
            uint32_t sz = 0;
            if (idx < 1584) {
                int ci = idx / 528; int r = idx - ci*528;
                int iy = r / 24, ix = r - iy*24;
                int gy = oy0 - 3 + iy, gx = ox0 - 3 + ix;
                if (ix < 22 && gy >= 0 && gy < HW && gx >= 0 && gx < HW) {
                    gp = xb + ci*HW2 + gy*HW + gx;
                    sz = 4;
                }
            }
            cp_async4(saddr, gp, sz);
        }
        asm volatile("cp.async.commit_group;" ::: "memory");
    };

    issue_halo(0, 0);

    for (int t = 0; t < C1_TPC; ++t) {
        int ox0 = oxbase + t*16;
        asm volatile("cp.async.wait_group 0;" ::: "memory");
        __syncthreads();                       // hbuf[t&1] ready; prev stage reads done

        // build shifted pairs hp[i] = (h[i], h[i+1]) in fp16
        {
            const float* hb = hbuf + (t & 1)*1992;
            for (int idx = tid; idx < 1984; idx += 256) {
                __half2 p = __floats2half2_rn(hb[idx], hb[idx+1]);
                hp[idx] = *(uint32_t*)&p;
            }
        }
        __syncthreads();                       // hp ready

        if (t + 1 < C1_TPC) issue_halo(t + 1, (t + 1) & 1);
        else asm volatile("cp.async.commit_group;" ::: "memory");

        float d[2][8][4];
        #pragma unroll
        for (int i = 0; i < 2; ++i)
            #pragma unroll
            for (int j = 0; j < 8; ++j)
                #pragma unroll
                for (int q = 0; q < 4; ++q) d[i][j][q] = 0.f;

        #pragma unroll 4
        for (int kc = 0; kc < 12; ++kc) {
            int klo = (kc >> 2)*528 + (kc & 3)*48 + 2*ac;
            int khi = klo + 24;
            uint32_t a[2][4];
            a[0][0] = hp[bo0 + klo];
            a[0][1] = hp[bo1 + klo];
            a[0][2] = hp[bo0 + khi];
            a[0][3] = hp[bo1 + khi];
            a[1][0] = hp[bo2 + klo];
            a[1][1] = hp[bo3 + klo];
            a[1][2] = hp[bo2 + khi];
            a[1][3] = hp[bo3 + khi];
            uint32_t bf[8][2];
            #pragma unroll
            for (int jp = 0; jp < 4; ++jp) {
                uint4 wv = wf[(kc*4 + jp)*32 + lane];
                bf[2*jp  ][0] = wv.x; bf[2*jp  ][1] = wv.y;
                bf[2*jp+1][0] = wv.z; bf[2*jp+1][1] = wv.w;
            }
            #pragma unroll
            for (int i = 0; i < 2; ++i)
                #pragma unroll
                for (int j = 0; j < 8; ++j)
                    mma_f16(d[i][j], a[i], bf[j]);
        }

        // stage D -> smem [oc][pixel], stride 261
        #pragma unroll
        for (int i = 0; i < 2; ++i) {
            #pragma unroll
            for (int rr = 0; rr < 2; ++rr) {
                int pix = m0 + 16*i + 8*rr + lq;
                #pragma unroll
                for (int j = 0; j < 8; ++j) {
                    int oc = 8*j + 2*ac;
                    stg[oc*261 + pix]     = d[i][j][2*rr + 0];
                    stg[(oc+1)*261 + pix] = d[i][j][2*rr + 1];
                }
            }
        }
        __syncthreads();                       // stage ready; hp reads done

        // channel-last fp16 store
        {
            int c = tid & 7;
            int pbase = tid >> 3;
            #pragma unroll
            for (int it = 0; it < 8; ++it) {
                int p = pbase + 32*it;
                uint32_t hh[4];
                #pragma unroll
                for (int q = 0; q < 4; ++q) {
                    int oc = 8*c + 2*q;
                    float v0 = stg[oc*261 + p]     + bias[oc];
                    float v1 = stg[(oc+1)*261 + p] + bias[oc+1];
                    __half2 hv = __floats2half2_rn(v0, v1);
                    hh[q] = *(uint32_t*)&hv;
                }
                int py = p >> 4, px = p & 15;
                size_t gp = (size_t)(oy0 + py)*HW + (ox0 + px);
                *(uint4*)(g_t1h + ((size_t)img*HW2 + gp)*64 + c*8) = *(uint4*)hh;
            }
        }
    }
}

// ---------------- conv2: 3x3, 64->2, pad 1 via fp16 mma.sync ----------------
__global__ __launch_bounds__(256) void k_conv2(const float* __restrict__ b2) {
    __shared__ __half sH[10*1296];        // halo [hy][hx(stride 72)][ci]
    __shared__ uint32_t sBf[36*64];       // B fragments
    __shared__ float sb2[2];
    int tid = threadIdx.x;
    int img = blockIdx.z;
    int oy0 = blockIdx.y*8, ox0 = blockIdx.x*16;

    if (tid < 2) sb2[tid] = b2[tid];
    for (int i = tid; i < 36*64; i += 256) sBf[i] = g_w2frag[i];
    for (int i = tid; i < 1440; i += 256) {
        int cg = i & 7; int rest = i >> 3;
        int hxp = rest % 18, hy = rest / 18;
        int gy = oy0 - 1 + hy, gx = ox0 - 1 + hxp;
        uint4 v = make_uint4(0,0,0,0);
        if (gy >= 0 && gy < HW && gx >= 0 && gx < HW)
            v = *(const uint4*)(g_t1h + ((size_t)img*HW2 + (size_t)gy*HW + gx)*64 + cg*8);
        *(uint4*)&sH[hy*1296 + hxp*72 + cg*8] = v;
    }
    __syncthreads();

    int wid = tid >> 5, lane = tid & 31;
    int ac = lane & 3, lq = lane >> 2;
    float d[4] = {0.f, 0.f, 0.f, 0.f};

    #pragma unroll
    for (int kc = 0; kc < 36; ++kc) {
        int tap = kc >> 2;
        int kh = tap/3, kw = tap - kh*3;
        int cig = (kc & 3)*16;
        int hy = wid + kh;
        int base = hy*1296 + kw*72 + cig + 2*ac;
        uint32_t a[4];
        a[0] = *(const uint32_t*)&sH[base + lq*72];
        a[1] = *(const uint32_t*)&sH[base + (lq+8)*72];
        a[2] = *(const uint32_t*)&sH[base + lq*72 + 8];
        a[3] = *(const uint32_t*)&sH[base + (lq+8)*72 + 8];
        uint2 bb = *(const uint2*)&sBf[kc*64 + lane*2];
        uint32_t bf[2] = {bb.x, bb.y};
        mma_f16(d, a, bf);
    }

    if (ac == 0) {
        float* o0 = g_ini + ((size_t)img*2 + 0)*HW2;
        float* o1 = g_ini + ((size_t)img*2 + 1)*HW2;
        int gy = oy0 + wid;
        int g0 = gy*HW + ox0 + lq;
        o0[g0]     = d[0] + sb2[0];
        o1[g0]     = d[1] + sb2[1];
        o0[g0 + 8] = d[2] + sb2[0];
        o1[g0 + 8] = d[3] + sb2[1];
    }
}

// ---------------- fea: 1x1 conv 3->2, /4, vectorized ----------------
__global__ __launch_bounds__(256) void k_fea(const float* __restrict__ x,
        const float* __restrict__ wfm, const float* __restrict__ bfm) {
    int idx = blockIdx.x*256 + threadIdx.x;
    int img = idx / (HW2/4);
    int p4 = (idx - img*(HW2/4)) * 4;
    const float* xb = x + (size_t)img*CIN*HW2 + p4;
    float4 x0 = *(const float4*)xb;
    float4 x1 = *(const float4*)(xb + HW2);
    float4 x2 = *(const float4*)(xb + 2*HW2);
    #pragma unroll
    for (int c = 0; c < 2; ++c) {
        float f0 = wfm[c*3+0], f1 = wfm[c*3+1], f2 = wfm[c*3+2], fb = bfm[c];
        float4 o;
        o.x = (x0.x*f0 + x1.x*f1 + x2.x*f2 + fb)*0.25f;
        o.y = (x0.y*f0 + x1.y*f1 + x2.y*f2 + fb)*0.25f;
        o.z = (x0.z*f0 + x1.z*f1 + x2.z*f2 + fb)*0.25f;
        o.w = (x0.w*f0 + x1.w*f1 + x2.w*f2 + fb)*0.25f;
        *(float4*)(g_fea + ((size_t)img*2 + c)*HW2 + p4) = o;
    }
}

// ---------------- trans: relu(M @ v) per patch, via mma.sync ----------------
#define TR_STR 108
#define TR_SMEM ((104*TR_STR + 128*TR_STR)*4)

template<int J0, int NJ>
__device__ __forceinline__ void trans_warp(const uint32_t* uBM, const uint32_t* uA,
                                           float* db, int m0, int lq, int ac) {
    float d[2][NJ][4];
    #pragma unroll
    for (int i = 0; i < 2; ++i)
        #pragma unroll
        for (int j = 0; j < NJ; ++j)
            #pragma unroll
            for (int q = 0; q < 4; ++q) d[i][j][q] = 0.f;

    #pragma unroll
    for (int kc = 0; kc < 13; ++kc) {
        int k0 = kc*8;
        uint32_t a[2][4], bf[NJ][2];
        #pragma unroll
        for (int i = 0; i < 2; ++i) {
            const uint32_t* base = uA + (m0 + 16*i + lq)*TR_STR + k0 + ac;
            a[i][0] = base[0];
            a[i][1] = base[8*TR_STR];
            a[i][2] = base[4];
            a[i][3] = base[8*TR_STR + 4];
        }
        #pragma unroll
        for (int j = 0; j < NJ; ++j) {
            const uint32_t* base = uBM + (8*(J0 + j) + lq)*TR_STR + k0 + ac;
            bf[j][0] = base[0];
            bf[j][1] = base[4];
        }
        #pragma unroll
        for (int i = 0; i < 2; ++i)
            #pragma unroll
            for (int j = 0; j < NJ; ++j)
                mma_tf32(d[i][j], a[i], bf[j]);
    }

    #pragma unroll
    for (int i = 0; i < 2; ++i) {
        #pragma unroll
        for (int rr = 0; rr < 2; ++rr) {
            int row = m0 + 16*i + lq + 8*rr;
            #pragma unroll
            for (int j = 0; j < NJ; ++j) {
                int col = 8*(J0 + j) + 2*ac;
                float2 v = make_float2(fmaxf(d[i][j][2*rr + 0], 0.f),
                                       fmaxf(d[i][j][2*rr + 1], 0.f));
                *(float2*)&db[(size_t)row*P2P + col] = v;
            }
        }
    }
}

__global__ __launch_bounds__(256) void k_trans() {
    extern __shared__ uint32_t smt[];
    uint32_t* uBM = smt;
    uint32_t* uA  = smt + 104*TR_STR;
    int tid = threadIdx.x;
    int img = blockIdx.y;
    int l0 = blockIdx.x * 128;
    const float* src = (blockIdx.z == 0) ? g_ini : g_fea;
    float* dst = (blockIdx.z == 0) ? g_UI : g_UF;

    for (int idx = tid; idx < 104*104; idx += 256) {
        int p = idx / 104, k = idx - p*104;
        uBM[p*TR_STR + k] = (p < P2 && k < P2) ? g_M[p*P2 + k] : 0u;
    }
    const float* sb = src + img*HW2;
    for (int idx = tid; idx < 128*104; idx += 256) {
        int pi = idx / 104, k = idx - pi*104;
        float v = 0.f;
        if (k < P2) {
            int l = l0 + pi;
            int py = k / PS, px = k - py*PS;
            v = sb[((l >> 5)*PS + py)*HW + (l & 31)*PS + px];
        }
        uA[pi*TR_STR + k] = f2tf32(v);
    }
    __syncthreads();

    int wid = tid >> 5, lane = tid & 31;
    int m0 = (wid & 3) * 32;
    int ac = lane & 3, lq = lane >> 2;
    float* db = dst + (size_t)img*NPATCH*P2P + (size_t)l0*P2P;
    if (wid < 4) trans_warp<0, 7>(uBM, uA, db, m0, lq, ac);
    else         trans_warp<7, 6>(uBM, uA, db, m0, lq, ac);
}

// ---------------- att: batched 1024x1024x100 NT-GEMM via mma.sync, /100 ----------------
#define AT_STR 108
#define ATT_SMEM (2*128*AT_STR*4)
__global__ __launch_bounds__(256) void k_att(float* __restrict__ out) {
    extern __shared__ float sma[];
    float* sA = sma;
    float* sB = sma + 128*AT_STR;
    int tid = threadIdx.x;
    int wid = tid >> 5, lane = tid & 31;
    int img = blockIdx.z;
    int gl0 = blockIdx.y*128, gm0 = blockIdx.x*128;
    const float* UI = g_UI + (size_t)img*NPATCH*P2P;
    const float* UF = g_UF + (size_t)img*NPATCH*P2P;

    for (int it = tid; it < 128*26; it += 256) {
        int rr = it/26, k0 = (it - rr*26) << 2;
        float4 va = *(const float4*)&UI[(size_t)(gl0 + rr)*P2P + k0];
        *(uint4*)&sA[rr*AT_STR + k0] =
            make_uint4(f2tf32(va.x), f2tf32(va.y), f2tf32(va.z), f2tf32(va.w));
        float4 vb = *(const float4*)&UF[(size_t)(gm0 + rr)*P2P + k0];
        *(uint4*)&sB[rr*AT_STR + k0] =
            make_uint4(f2tf32(vb.x), f2tf32(vb.y), f2tf32(vb.z), f2tf32(vb.w));
    }
    __syncthreads();

    int m0 = (wid & 3)*32, n0 = (wid >> 2)*64;
    int ac = lane & 3, lq = lane >> 2;
    float d[2][8][4];
    #pragma unroll
    for (int i = 0; i < 2; ++i)
        #pragma unroll
        for (int j = 0; j < 8; ++j)
            #pragma unroll
            for (int q = 0; q < 4; ++q) d[i][j][q] = 0.f;

    const uint32_t* uA = (const uint32_t*)sA;
    const uint32_t* uB = (const uint32_t*)sB;

    #pragma unroll
    for (int kc = 0; kc < 13; ++kc) {
        int k0 = kc*8;
        uint32_t a[2][4], bf[8][2];
        #pragma unroll
        for (int i = 0; i < 2; ++i) {
            const uint32_t* base = uA + (m0 + 16*i + lq)*AT_STR + k0 + ac;
            a[i][0] = base[0];
            a[i][1] = base[8*AT_STR];
            a[i][2] = base[4];
            a[i][3] = base[8*AT_STR + 4];
        }
        #pragma unroll
        for (int j = 0; j < 8; ++j) {
            const uint32_t* base = uB + (n0 + 8*j + lq)*AT_STR + k0 + ac;
            bf[j][0] = base[0];
            bf[j][1] = base[4];
        }
        #pragma unroll
        for (int i = 0; i < 2; ++i)
            #pragma unroll
            for (int j = 0; j < 8; ++j)
                mma_tf32(d[i][j], a[i], bf[j]);
    }

    #pragma unroll
    for (int i = 0; i < 2; ++i) {
        #pragma unroll
        for (int rr = 0; rr < 2; ++rr) {
            int l = gl0 + m0 + 16*i + lq + 8*rr;
            #pragma unroll
            for (int j = 0; j < 8; ++j) {
                int m = gm0 + n0 + 8*j + 2*ac;
                float2 v = make_float2(d[i][j][2*rr + 0]*0.01f, d[i][j][2*rr + 1]*0.01f);
                *(float2*)&out[((long)img*NPATCH + l)*NPATCH + m] = v;
            }
        }
    }
}

extern "C" void kernel_launch(void* const* d_in, const int* in_sizes, int n_in,
                              void* d_out, int out_size) {
    const float* x   = (const float*)d_in[0];
    const float* w1c = (const float*)d_in[1];
    const float* b1c = (const float*)d_in[2];
    const float* w2c = (const float*)d_in[3];
    const float* b2c = (const float*)d_in[4];
    const float* wfm = (const float*)d_in[5];
    const float* bfm = (const float*)d_in[6];
    const float* wl1 = (const float*)d_in[7];
    const float* wl2 = (const float*)d_in[8];
    float* out = (float*)d_out;

    static bool attr_set = false;
    if (!attr_set) {
        cudaFuncSetAttribute(k_conv1, cudaFuncAttributeMaxDynamicSharedMemorySize, C1_SMEMB);
        cudaFuncSetAttribute(k_trans, cudaFuncAttributeMaxDynamicSharedMemorySize, TR_SMEM);
        cudaFuncSetAttribute(k_att,   cudaFuncAttributeMaxDynamicSharedMemorySize, ATT_SMEM);
        attr_set = true;
    }

    k_buildM<<<P2, 128>>>(wl1, wl2);
    k_prepw<<<24, 256>>>(w1c);
    k_prepw2<<<9, 256>>>(w2c);
    k_conv1<<<dim3(5,20,BATCH), 256, C1_SMEMB>>>(x, b1c);
    k_conv2<<<dim3(20,40,BATCH), 256>>>(b2c);
    k_fea<<<800, 256>>>(x, wfm, bfm);
    k_trans<<<dim3(8, IMGS, 2), 256, TR_SMEM>>>();
    k_att<<<dim3(8,8,IMGS), 256, ATT_SMEM>>>(out);
}

// round 9
// speedup vs baseline: 4.3836x; 1.1098x over previous
#include <cuda_runtime.h>
#include <cuda_fp16.h>
#include <cstdint>

#define BATCH 8
#define CIN 3
#define HW 320
#define HW2 (HW*HW)
#define C1 64
#define PS 10
#define P2 100
#define P2P 112
#define NPATCH 1024
#define IMGS 16

// scratch (device globals — no runtime allocation)
__device__ __half g_t1h[(size_t)BATCH*HW2*C1];   // conv1 out, fp16, CHANNEL-LAST [img][pix][ci]
__device__ float g_ini[IMGS*HW2];
__device__ float g_fea[IMGS*HW2];
__device__ uint32_t g_M[P2*P2];                  // (W2@W1) row-major [p][k], tf32 bits
__device__ uint32_t g_wfrag[12*4*32*4];          // conv1 weights, fp16 fragment order (K'=192)
__device__ uint32_t g_w2frag[36*64];             // conv2 weights, fragment-ordered fp16x2
__device__ __half g_UI[(size_t)IMGS*NPATCH*P2P]; // fp16, K padded to 112
__device__ __half g_UF[(size_t)IMGS*NPATCH*P2P];

// ---------------- helpers ----------------
__device__ __forceinline__ uint32_t f2tf32(float f) {
    uint32_t r;
    asm("cvt.rna.tf32.f32 %0, %1;" : "=r"(r) : "f"(f));
    return r;
}
__device__ __forceinline__ void mma_tf32(float* d, const uint32_t* a, const uint32_t* b) {
    asm volatile(
        "mma.sync.aligned.m16n8k8.row.col.f32.tf32.tf32.f32 "
        "{%0,%1,%2,%3}, {%4,%5,%6,%7}, {%8,%9}, {%0,%1,%2,%3};"
        : "+f"(d[0]), "+f"(d[1]), "+f"(d[2]), "+f"(d[3])
        : "r"(a[0]), "r"(a[1]), "r"(a[2]), "r"(a[3]), "r"(b[0]), "r"(b[1]));
}
__device__ __forceinline__ void mma_f16(float* d, const uint32_t* a, const uint32_t* b) {
    asm volatile(
        "mma.sync.aligned.m16n8k16.row.col.f32.f16.f16.f32 "
        "{%0,%1,%2,%3}, {%4,%5,%6,%7}, {%8,%9}, {%0,%1,%2,%3};"
        : "+f"(d[0]), "+f"(d[1]), "+f"(d[2]), "+f"(d[3])
        : "r"(a[0]), "r"(a[1]), "r"(a[2]), "r"(a[3]), "r"(b[0]), "r"(b[1]));
}
__device__ __forceinline__ void cp_async4(uint32_t saddr, const void* gptr, uint32_t src_sz) {
    asm volatile("cp.async.ca.shared.global [%0], [%1], 4, %2;"
                 :: "r"(saddr), "l"(gptr), "r"(src_sz));
}

// ---------------- M = w_lin2 @ w_lin1 (row-major [p][k], tf32 bits) ----------------
__global__ void k_buildM(const float* __restrict__ w1, const float* __restrict__ w2) {
    int p = blockIdx.x;
    int k = threadIdx.x;
    if (k >= P2) return;
    float acc = 0.f;
    for (int q = 0; q < 2*P2; ++q)
        acc += w2[p*2*P2 + q] * w1[q*P2 + k];
    g_M[p*P2 + k] = f2tf32(acc);
}

// ---------------- prepack conv1 weights: fp16 m16n8k16 B-fragments, K'=192 ----------------
__global__ void k_prepw(const float* __restrict__ w) {
    int idx = blockIdx.x*256 + threadIdx.x;   // 6144 total
    int c = idx & 3, lane = (idx >> 2) & 31, jp = (idx >> 7) & 3, kc = idx >> 9;
    int j = 2*jp + (c >> 1), r = c & 1;
    int oc = 8*j + (lane >> 2);
    __half h2[2];
    #pragma unroll
    for (int hh = 0; hh < 2; ++hh) {
        int k = 16*kc + 2*(lane & 3) + 8*r + hh;
        int ci = k >> 6, kh = (k >> 3) & 7, kw = k & 7;
        float v = (kh < 7 && kw < 7) ? w[oc*147 + ci*49 + kh*7 + kw] : 0.f;
        h2[hh] = __float2half_rn(v);
    }
    g_wfrag[idx] = *(uint32_t*)h2;
}

// ---------------- prepack conv2 weights (fp16 m16n8k16 B-fragment order) ----------------
__global__ void k_prepw2(const float* __restrict__ w2) {
    int idx = blockIdx.x*256 + threadIdx.x;   // 2304 total
    if (idx >= 36*64) return;
    int r = idx & 1, lane = (idx >> 1) & 31, kc = idx >> 6;
    int n = lane >> 2;
    int tap = kc >> 2, kh = tap/3, kw = tap - kh*3;
    __half h[2];
    #pragma unroll
    for (int hh = 0; hh < 2; ++hh) {
        int kl = (lane & 3)*2 + hh + 8*r;
        int ci = (kc & 3)*16 + kl;
        float v = (n < 2) ? w2[((n*64 + ci)*3 + kh)*3 + kw] : 0.f;
        h[hh] = __float2half_rn(v);
    }
    g_w2frag[idx] = *(uint32_t*)h;
}

// ---------------- conv1: 7x7, 3->64, pad 3 via fp16 mma.sync, cp.async pipelined ----------------
// CTA 256 thr, 4 tiles of 16x16 pixels along x; K'=192 (12 chunks of 16); 2 CTAs/SM
#define C1_TPC 4
#define OFS_STG 0            // 64 x 261 floats
#define OFS_HP  16704        // 1984 pairs
#define OFS_HB  18688        // 2 x 1992 fp32 halo
#define OFS_BIAS 22672       // 64
#define C1_SMEMB (22736*4)

__global__ __launch_bounds__(256, 2) void k_conv1(const float* __restrict__ x,
                                                  const float* __restrict__ b) {
    extern __shared__ uint32_t smw[];
    float*    stg  = (float*)(smw + OFS_STG);
    uint32_t* hp   = smw + OFS_HP;
    float*    hbuf = (float*)(smw + OFS_HB);
    float*    bias = (float*)(smw + OFS_BIAS);

    int tid = threadIdx.x;
    int img = blockIdx.z;
    int oy0 = blockIdx.y*16;
    int oxbase = blockIdx.x*(16*C1_TPC);
    const float* xb = x + img*CIN*HW2;

    if (tid < C1) bias[tid] = b[tid];

    int wid = tid >> 5, lane = tid & 31;
    int m0 = wid * 32;
    int ac = lane & 3, lq = lane >> 2;
    int rr0 = m0 + lq;
    int bo0 = ((rr0    ) >> 4)*24 + ((rr0    ) & 15);
    int bo1 = ((rr0 + 8) >> 4)*24 + ((rr0 + 8) & 15);
    int bo2 = ((rr0 +16) >> 4)*24 + ((rr0 +16) & 15);
    int bo3 = ((rr0 +24) >> 4)*24 + ((rr0 +24) & 15);
    const uint4* wf = (const uint4*)g_wfrag;

    auto issue_halo = [&](int t, int buf) {
        int ox0 = oxbase + t*16;
        float* hb = hbuf + buf*1992;
        for (int idx = tid; idx < 1992; idx += 256) {
            uint32_t saddr = (uint32_t)__cvta_generic_to_shared(hb + idx);
            const float* gp = xb;
            uint32_t sz = 0;
            if (idx < 1584) {
                int ci = idx / 528; int r = idx - ci*528;
                int iy = r / 24, ix = r - iy*24;
                int gy = oy0 - 3 + iy, gx = ox0 - 3 + ix;
                if (ix < 22 && gy >= 0 && gy < HW && gx >= 0 && gx < HW) {
                    gp = xb + ci*HW2 + gy*HW + gx;
                    sz = 4;
                }
            }
            cp_async4(saddr, gp, sz);
        }
        asm volatile("cp.async.commit_group;" ::: "memory");
    };

    issue_halo(0, 0);

    for (int t = 0; t < C1_TPC; ++t) {
        int ox0 = oxbase + t*16;
        asm volatile("cp.async.wait_group 0;" ::: "memory");
        __syncthreads();

        {
            const float* hb = hbuf + (t & 1)*1992;
            for (int idx = tid; idx < 1984; idx += 256) {
                __half2 p = __floats2half2_rn(hb[idx], hb[idx+1]);
                hp[idx] = *(uint32_t*)&p;
            }
        }
        __syncthreads();

        if (t + 1 < C1_TPC) issue_halo(t + 1, (t + 1) & 1);
        else asm volatile("cp.async.commit_group;" ::: "memory");

        float d[2][8][4];
        #pragma unroll
        for (int i = 0; i < 2; ++i)
            #pragma unroll
            for (int j = 0; j < 8; ++j)
                #pragma unroll
                for (int q = 0; q < 4; ++q) d[i][j][q] = 0.f;

        #pragma unroll 4
        for (int kc = 0; kc < 12; ++kc) {
            int klo = (kc >> 2)*528 + (kc & 3)*48 + 2*ac;
            int khi = klo + 24;
            uint32_t a[2][4];
            a[0][0] = hp[bo0 + klo];
            a[0][1] = hp[bo1 + klo];
            a[0][2] = hp[bo0 + khi];
            a[0][3] = hp[bo1 + khi];
            a[1][0] = hp[bo2 + klo];
            a[1][1] = hp[bo3 + klo];
            a[1][2] = hp[bo2 + khi];
            a[1][3] = hp[bo3 + khi];
            uint32_t bf[8][2];
            #pragma unroll
            for (int jp = 0; jp < 4; ++jp) {
                uint4 wv = wf[(kc*4 + jp)*32 + lane];
                bf[2*jp  ][0] = wv.x; bf[2*jp  ][1] = wv.y;
                bf[2*jp+1][0] = wv.z; bf[2*jp+1][1] = wv.w;
            }
            #pragma unroll
            for (int i = 0; i < 2; ++i)
                #pragma unroll
                for (int j = 0; j < 8; ++j)
                    mma_f16(d[i][j], a[i], bf[j]);
        }

        // stage D -> smem [oc][pixel], stride 261
        #pragma unroll
        for (int i = 0; i < 2; ++i) {
            #pragma unroll
            for (int rr = 0; rr < 2; ++rr) {
                int pix = m0 + 16*i + 8*rr + lq;
                #pragma unroll
                for (int j = 0; j < 8; ++j) {
                    int oc = 8*j + 2*ac;
                    stg[oc*261 + pix]     = d[i][j][2*rr + 0];
                    stg[(oc+1)*261 + pix] = d[i][j][2*rr + 1];
                }
            }
        }
        __syncthreads();

        // channel-last fp16 store
        {
            int c = tid & 7;
            int pbase = tid >> 3;
            #pragma unroll
            for (int it = 0; it < 8; ++it) {
                int p = pbase + 32*it;
                uint32_t hh[4];
                #pragma unroll
                for (int q = 0; q < 4; ++q) {
                    int oc = 8*c + 2*q;
                    float v0 = stg[oc*261 + p]     + bias[oc];
                    float v1 = stg[(oc+1)*261 + p] + bias[oc+1];
                    __half2 hv = __floats2half2_rn(v0, v1);
                    hh[q] = *(uint32_t*)&hv;
                }
                int py = p >> 4, px = p & 15;
                size_t gp = (size_t)(oy0 + py)*HW + (ox0 + px);
                *(uint4*)(g_t1h + ((size_t)img*HW2 + gp)*64 + c*8) = *(uint4*)hh;
            }
        }
    }
}

// ---------------- conv2: 3x3, 64->2, pad 1 via fp16 mma.sync ----------------
__global__ __launch_bounds__(256) void k_conv2(const float* __restrict__ b2) {
    __shared__ __half sH[10*1296];        // halo [hy][hx(stride 72)][ci]
    __shared__ uint32_t sBf[36*64];       // B fragments
    __shared__ float sb2[2];
    int tid = threadIdx.x;
    int img = blockIdx.z;
    int oy0 = blockIdx.y*8, ox0 = blockIdx.x*16;

    if (tid < 2) sb2[tid] = b2[tid];
    for (int i = tid; i < 36*64; i += 256) sBf[i] = g_w2frag[i];
    for (int i = tid; i < 1440; i += 256) {
        int cg = i & 7; int rest = i >> 3;
        int hxp = rest % 18, hy = rest / 18;
        int gy = oy0 - 1 + hy, gx = ox0 - 1 + hxp;
        uint4 v = make_uint4(0,0,0,0);
        if (gy >= 0 && gy < HW && gx >= 0 && gx < HW)
            v = *(const uint4*)(g_t1h + ((size_t)img*HW2 + (size_t)gy*HW + gx)*64 + cg*8);
        *(uint4*)&sH[hy*1296 + hxp*72 + cg*8] = v;
    }
    __syncthreads();

    int wid = tid >> 5, lane = tid & 31;
    int ac = lane & 3, lq = lane >> 2;
    float d[4] = {0.f, 0.f, 0.f, 0.f};

    #pragma unroll
    for (int kc = 0; kc < 36; ++kc) {
        int tap = kc >> 2;
        int kh = tap/3, kw = tap - kh*3;
        int cig = (kc & 3)*16;
        int hy = wid + kh;
        int base = hy*1296 + kw*72 + cig + 2*ac;
        uint32_t a[4];
        a[0] = *(const uint32_t*)&sH[base + lq*72];
        a[1] = *(const uint32_t*)&sH[base + (lq+8)*72];
        a[2] = *(const uint32_t*)&sH[base + lq*72 + 8];
        a[3] = *(const uint32_t*)&sH[base + (lq+8)*72 + 8];
        uint2 bb = *(const uint2*)&sBf[kc*64 + lane*2];
        uint32_t bf[2] = {bb.x, bb.y};
        mma_f16(d, a, bf);
    }

    if (ac == 0) {
        float* o0 = g_ini + ((size_t)img*2 + 0)*HW2;
        float* o1 = g_ini + ((size_t)img*2 + 1)*HW2;
        int gy = oy0 + wid;
        int g0 = gy*HW + ox0 + lq;
        o0[g0]     = d[0] + sb2[0];
        o1[g0]     = d[1] + sb2[1];
        o0[g0 + 8] = d[2] + sb2[0];
        o1[g0 + 8] = d[3] + sb2[1];
    }
}

// ---------------- fea: 1x1 conv 3->2, /4, vectorized ----------------
__global__ __launch_bounds__(256) void k_fea(const float* __restrict__ x,
        const float* __restrict__ wfm, const float* __restrict__ bfm) {
    int idx = blockIdx.x*256 + threadIdx.x;
    int img = idx / (HW2/4);
    int p4 = (idx - img*(HW2/4)) * 4;
    const float* xb = x + (size_t)img*CIN*HW2 + p4;
    float4 x0 = *(const float4*)xb;
    float4 x1 = *(const float4*)(xb + HW2);
    float4 x2 = *(const float4*)(xb + 2*HW2);
    #pragma unroll
    for (int c = 0; c < 2; ++c) {
        float f0 = wfm[c*3+0], f1 = wfm[c*3+1], f2 = wfm[c*3+2], fb = bfm[c];
        float4 o;
        o.x = (x0.x*f0 + x1.x*f1 + x2.x*f2 + fb)*0.25f;
        o.y = (x0.y*f0 + x1.y*f1 + x2.y*f2 + fb)*0.25f;
        o.z = (x0.z*f0 + x1.z*f1 + x2.z*f2 + fb)*0.25f;
        o.w = (x0.w*f0 + x1.w*f1 + x2.w*f2 + fb)*0.25f;
        *(float4*)(g_fea + ((size_t)img*2 + c)*HW2 + p4) = o;
    }
}

// ---------------- trans: relu(M @ v) per patch, via mma.sync, fp16 out ----------------
#define TR_STR 108
#define TR_SMEM ((104*TR_STR + 128*TR_STR)*4)

template<int J0, int NJ>
__device__ __forceinline__ void trans_warp(const uint32_t* uBM, const uint32_t* uA,
                                           __half* db, int m0, int lq, int ac) {
    float d[2][NJ][4];
    #pragma unroll
    for (int i = 0; i < 2; ++i)
        #pragma unroll
        for (int j = 0; j < NJ; ++j)
            #pragma unroll
            for (int q = 0; q < 4; ++q) d[i][j][q] = 0.f;

    #pragma unroll
    for (int kc = 0; kc < 13; ++kc) {
        int k0 = kc*8;
        uint32_t a[2][4], bf[NJ][2];
        #pragma unroll
        for (int i = 0; i < 2; ++i) {
            const uint32_t* base = uA + (m0 + 16*i + lq)*TR_STR + k0 + ac;
            a[i][0] = base[0];
            a[i][1] = base[8*TR_STR];
            a[i][2] = base[4];
            a[i][3] = base[8*TR_STR + 4];
        }
        #pragma unroll
        for (int j = 0; j < NJ; ++j) {
            const uint32_t* base = uBM + (8*(J0 + j) + lq)*TR_STR + k0 + ac;
            bf[j][0] = base[0];
            bf[j][1] = base[4];
        }
        #pragma unroll
        for (int i = 0; i < 2; ++i)
            #pragma unroll
            for (int j = 0; j < NJ; ++j)
                mma_tf32(d[i][j], a[i], bf[j]);
    }

    #pragma unroll
    for (int i = 0; i < 2; ++i) {
        #pragma unroll
        for (int rr = 0; rr < 2; ++rr) {
            int row = m0 + 16*i + lq + 8*rr;
            #pragma unroll
            for (int j = 0; j < NJ; ++j) {
                int col = 8*(J0 + j) + 2*ac;
                __half2 hv = __floats2half2_rn(fmaxf(d[i][j][2*rr + 0], 0.f),
                                               fmaxf(d[i][j][2*rr + 1], 0.f));
                *(uint32_t*)&db[(size_t)row*P2P + col] = *(uint32_t*)&hv;
            }
        }
    }
}

__global__ __launch_bounds__(256) void k_trans() {
    extern __shared__ uint32_t smt[];
    uint32_t* uBM = smt;
    uint32_t* uA  = smt + 104*TR_STR;
    int tid = threadIdx.x;
    int img = blockIdx.y;
    int l0 = blockIdx.x * 128;
    const float* src = (blockIdx.z == 0) ? g_ini : g_fea;
    __half* dst = (blockIdx.z == 0) ? g_UI : g_UF;

    for (int idx = tid; idx < 104*104; idx += 256) {
        int p = idx / 104, k = idx - p*104;
        uBM[p*TR_STR + k] = (p < P2 && k < P2) ? g_M[p*P2 + k] : 0u;
    }
    const float* sb = src + img*HW2;
    for (int idx = tid; idx < 128*104; idx += 256) {
        int pi = idx / 104, k = idx - pi*104;
        float v = 0.f;
        if (k < P2) {
            int l = l0 + pi;
            int py = k / PS, px = k - py*PS;
            v = sb[((l >> 5)*PS + py)*HW + (l & 31)*PS + px];
        }
        uA[pi*TR_STR + k] = f2tf32(v);
    }
    __syncthreads();

    int wid = tid >> 5, lane = tid & 31;
    int m0 = (wid & 3) * 32;
    int ac = lane & 3, lq = lane >> 2;
    __half* db = dst + (size_t)img*NPATCH*P2P + (size_t)l0*P2P;
    // zero K-pad cols 104..111 (as uint32: 4 per row)
    {
        uint32_t* d32 = (uint32_t*)db;
        for (int idx = tid; idx < 128*4; idx += 256)
            d32[(idx >> 2)*56 + 52 + (idx & 3)] = 0u;
    }
    if (wid < 4) trans_warp<0, 7>(uBM, uA, db, m0, lq, ac);
    else         trans_warp<7, 6>(uBM, uA, db, m0, lq, ac);
}

// ---------------- att: batched 1024x1024x112 NT-GEMM via fp16 mma.sync, /100 ----------------
#define AT_STR 68            // uint32 stride; 68 mod 32 == 4 -> conflict-free fragments
#define ATT_SMEM (2*128*AT_STR*4)
__global__ __launch_bounds__(256) void k_att(float* __restrict__ out) {
    extern __shared__ uint32_t sma[];
    uint32_t* sA = sma;
    uint32_t* sB = sma + 128*AT_STR;
    int tid = threadIdx.x;
    int wid = tid >> 5, lane = tid & 31;
    int img = blockIdx.z;
    int gl0 = blockIdx.y*128, gm0 = blockIdx.x*128;
    const __half* UI = g_UI + (size_t)img*NPATCH*P2P;
    const __half* UF = g_UF + (size_t)img*NPATCH*P2P;

    for (int it = tid; it < 128*14; it += 256) {
        int rr = it/14, c = it - rr*14;
        uint4 va = *(const uint4*)&UI[(size_t)(gl0 + rr)*P2P + c*8];
        *(uint4*)&sA[rr*AT_STR + c*4] = va;
        uint4 vb = *(const uint4*)&UF[(size_t)(gm0 + rr)*P2P + c*8];
        *(uint4*)&sB[rr*AT_STR + c*4] = vb;
    }
    __syncthreads();

    int m0 = (wid & 3)*32, n0 = (wid >> 2)*64;
    int ac = lane & 3, lq = lane >> 2;
    float d[2][8][4];
    #pragma unroll
    for (int i = 0; i < 2; ++i)
        #pragma unroll
        for (int j = 0; j < 8; ++j)
            #pragma unroll
            for (int q = 0; q < 4; ++q) d[i][j][q] = 0.f;

    #pragma unroll
    for (int kc = 0; kc < 7; ++kc) {
        int k0 = kc*8;
        uint32_t a[2][4], bf[8][2];
        #pragma unroll
        for (int i = 0; i < 2; ++i) {
            const uint32_t* base = sA + (m0 + 16*i + lq)*AT_STR + k0 + ac;
            a[i][0] = base[0];
            a[i][1] = base[8*AT_STR];
            a[i][2] = base[4];
            a[i][3] = base[8*AT_STR + 4];
        }
        #pragma unroll
        for (int j = 0; j < 8; ++j) {
            const uint32_t* base = sB + (n0 + 8*j + lq)*AT_STR + k0 + ac;
            bf[j][0] = base[0];
            bf[j][1] = base[4];
        }
        #pragma unroll
        for (int i = 0; i < 2; ++i)
            #pragma unroll
            for (int j = 0; j < 8; ++j)
                mma_f16(d[i][j], a[i], bf[j]);
    }

    #pragma unroll
    for (int i = 0; i < 2; ++i) {
        #pragma unroll
        for (int rr = 0; rr < 2; ++rr) {
            int l = gl0 + m0 + 16*i + lq + 8*rr;
            #pragma unroll
            for (int j = 0; j < 8; ++j) {
                int m = gm0 + n0 + 8*j + 2*ac;
                float2 v = make_float2(d[i][j][2*rr + 0]*0.01f, d[i][j][2*rr + 1]*0.01f);
                *(float2*)&out[((long)img*NPATCH + l)*NPATCH + m] = v;
            }
        }
    }
}

extern "C" void kernel_launch(void* const* d_in, const int* in_sizes, int n_in,
                              void* d_out, int out_size) {
    const float* x   = (const float*)d_in[0];
    const float* w1c = (const float*)d_in[1];
    const float* b1c = (const float*)d_in[2];
    const float* w2c = (const float*)d_in[3];
    const float* b2c = (const float*)d_in[4];
    const float* wfm = (const float*)d_in[5];
    const float* bfm = (const float*)d_in[6];
    const float* wl1 = (const float*)d_in[7];
    const float* wl2 = (const float*)d_in[8];
    float* out = (float*)d_out;

    static bool attr_set = false;
    if (!attr_set) {
        cudaFuncSetAttribute(k_conv1, cudaFuncAttributeMaxDynamicSharedMemorySize, C1_SMEMB);
        cudaFuncSetAttribute(k_trans, cudaFuncAttributeMaxDynamicSharedMemorySize, TR_SMEM);
        cudaFuncSetAttribute(k_att,   cudaFuncAttributeMaxDynamicSharedMemorySize, ATT_SMEM);
        attr_set = true;
    }

    k_buildM<<<P2, 128>>>(wl1, wl2);
    k_prepw<<<24, 256>>>(w1c);
    k_prepw2<<<9, 256>>>(w2c);
    k_conv1<<<dim3(5,20,BATCH), 256, C1_SMEMB>>>(x, b1c);
    k_conv2<<<dim3(20,40,BATCH), 256>>>(b2c);
    k_fea<<<800, 256>>>(x, wfm, bfm);
    k_trans<<<dim3(8, IMGS, 2), 256, TR_SMEM>>>();
    k_att<<<dim3(8,8,IMGS), 256, ATT_SMEM>>>(out);
}

// round 10
// speedup vs baseline: 4.6700x; 1.0653x over previous
#include <cuda_runtime.h>
#include <cuda_fp16.h>
#include <cstdint>

#define BATCH 8
#define CIN 3
#define HW 320
#define HW2 (HW*HW)
#define C1 64
#define PS 10
#define P2 100
#define P2P 112
#define NPATCH 1024
#define IMGS 16

// scratch (device globals — no runtime allocation)
__device__ __half g_t1h[(size_t)BATCH*HW2*C1];   // conv1 out, fp16, CHANNEL-LAST [img][pix][ci]
__device__ float g_ini[IMGS*HW2];
__device__ float g_fea[IMGS*HW2];
__device__ uint32_t g_M[P2*P2];                  // (W2@W1) row-major [p][k], tf32 bits
__device__ uint32_t g_wfrag[12*4*32*4];          // conv1 weights, fp16 fragment order (K'=192)
__device__ uint32_t g_w2frag[36*64];             // conv2 weights, fragment-ordered fp16x2
__device__ __half g_UI[(size_t)IMGS*NPATCH*P2P]; // fp16, K padded to 112
__device__ __half g_UF[(size_t)IMGS*NPATCH*P2P];

// ---------------- helpers ----------------
__device__ __forceinline__ uint32_t f2tf32(float f) {
    uint32_t r;
    asm("cvt.rna.tf32.f32 %0, %1;" : "=r"(r) : "f"(f));
    return r;
}
__device__ __forceinline__ void mma_tf32(float* d, const uint32_t* a, const uint32_t* b) {
    asm volatile(
        "mma.sync.aligned.m16n8k8.row.col.f32.tf32.tf32.f32 "
        "{%0,%1,%2,%3}, {%4,%5,%6,%7}, {%8,%9}, {%0,%1,%2,%3};"
        : "+f"(d[0]), "+f"(d[1]), "+f"(d[2]), "+f"(d[3])
        : "r"(a[0]), "r"(a[1]), "r"(a[2]), "r"(a[3]), "r"(b[0]), "r"(b[1]));
}
__device__ __forceinline__ void mma_f16(float* d, const uint32_t* a, const uint32_t* b) {
    asm volatile(
        "mma.sync.aligned.m16n8k16.row.col.f32.f16.f16.f32 "
        "{%0,%1,%2,%3}, {%4,%5,%6,%7}, {%8,%9}, {%0,%1,%2,%3};"
        : "+f"(d[0]), "+f"(d[1]), "+f"(d[2]), "+f"(d[3])
        : "r"(a[0]), "r"(a[1]), "r"(a[2]), "r"(a[3]), "r"(b[0]), "r"(b[1]));
}
__device__ __forceinline__ void cp_async4(uint32_t saddr, const void* gptr, uint32_t src_sz) {
    asm volatile("cp.async.ca.shared.global [%0], [%1], 4, %2;"
                 :: "r"(saddr), "l"(gptr), "r"(src_sz));
}

// ---------------- M = w_lin2 @ w_lin1 (row-major [p][k], tf32 bits) ----------------
__global__ void k_buildM(const float* __restrict__ w1, const float* __restrict__ w2) {
    int p = blockIdx.x;
    int k = threadIdx.x;
    if (k >= P2) return;
    float acc = 0.f;
    for (int q = 0; q < 2*P2; ++q)
        acc += w2[p*2*P2 + q] * w1[q*P2 + k];
    g_M[p*P2 + k] = f2tf32(acc);
}

// ---------------- prepack conv1 weights: fp16 m16n8k16 B-fragments, K'=192 ----------------
__global__ void k_prepw(const float* __restrict__ w) {
    int idx = blockIdx.x*256 + threadIdx.x;   // 6144 total
    int c = idx & 3, lane = (idx >> 2) & 31, jp = (idx >> 7) & 3, kc = idx >> 9;
    int j = 2*jp + (c >> 1), r = c & 1;
    int oc = 8*j + (lane >> 2);
    __half h2[2];
    #pragma unroll
    for (int hh = 0; hh < 2; ++hh) {
        int k = 16*kc + 2*(lane & 3) + 8*r + hh;
        int ci = k >> 6, kh = (k >> 3) & 7, kw = k & 7;
        float v = (kh < 7 && kw < 7) ? w[oc*147 + ci*49 + kh*7 + kw] : 0.f;
        h2[hh] = __float2half_rn(v);
    }
    g_wfrag[idx] = *(uint32_t*)h2;
}

// ---------------- prepack conv2 weights (fp16 m16n8k16 B-fragment order) ----------------
__global__ void k_prepw2(const float* __restrict__ w2) {
    int idx = blockIdx.x*256 + threadIdx.x;   // 2304 total
    if (idx >= 36*64) return;
    int r = idx & 1, lane = (idx >> 1) & 31, kc = idx >> 6;
    int n = lane >> 2;
    int tap = kc >> 2, kh = tap/3, kw = tap - kh*3;
    __half h[2];
    #pragma unroll
    for (int hh = 0; hh < 2; ++hh) {
        int kl = (lane & 3)*2 + hh + 8*r;
        int ci = (kc & 3)*16 + kl;
        float v = (n < 2) ? w2[((n*64 + ci)*3 + kh)*3 + kw] : 0.f;
        h[hh] = __float2half_rn(v);
    }
    g_w2frag[idx] = *(uint32_t*)h;
}

// ---------------- conv1: 7x7, 3->64, pad 3 via fp16 mma.sync, cp.async pipelined ----------------
// CTA 256 thr, 4 tiles of 16x16 pixels along x; K'=192 (12 chunks of 16); 2 CTAs/SM
// smem: weights 6144 | hp 1984 | hbuf 2x1992 | bias 64  (uint32 units)
#define C1_TPC 4
#define OFS_W   0
#define OFS_HP  6144
#define OFS_HB  8128
#define OFS_BIAS 12112
#define C1_SMEMB (12176*4)

__global__ __launch_bounds__(256, 2) void k_conv1(const float* __restrict__ x,
                                                  const float* __restrict__ b) {
    extern __shared__ uint32_t smw[];
    uint32_t* sW   = smw + OFS_W;
    uint32_t* hp   = smw + OFS_HP;
    float*    hbuf = (float*)(smw + OFS_HB);
    float*    bias = (float*)(smw + OFS_BIAS);

    int tid = threadIdx.x;
    int img = blockIdx.z;
    int oy0 = blockIdx.y*16;
    int oxbase = blockIdx.x*(16*C1_TPC);
    const float* xb = x + img*CIN*HW2;

    if (tid < C1) bias[tid] = b[tid];
    // weights -> smem once (conflict-free uint4 copy)
    for (int idx = tid; idx < 1536; idx += 256)
        ((uint4*)sW)[idx] = ((const uint4*)g_wfrag)[idx];
    __syncthreads();

    int wid = tid >> 5, lane = tid & 31;
    int m0 = wid * 32;
    int ac = lane & 3, lq = lane >> 2;
    int rr0 = m0 + lq;
    int bo0 = ((rr0    ) >> 4)*24 + ((rr0    ) & 15);
    int bo1 = ((rr0 + 8) >> 4)*24 + ((rr0 + 8) & 15);
    int bo2 = ((rr0 +16) >> 4)*24 + ((rr0 +16) & 15);
    int bo3 = ((rr0 +24) >> 4)*24 + ((rr0 +24) & 15);

    // bias pairs for this thread's columns, hoisted to registers
    float2 bv[8];
    #pragma unroll
    for (int j = 0; j < 8; ++j) {
        int oc = 8*j + 2*ac;
        bv[j] = make_float2(bias[oc], bias[oc+1]);
    }

    auto issue_halo = [&](int t, int buf) {
        int ox0 = oxbase + t*16;
        float* hb = hbuf + buf*1992;
        for (int idx = tid; idx < 1992; idx += 256) {
            uint32_t saddr = (uint32_t)__cvta_generic_to_shared(hb + idx);
            const float* gp = xb;
            uint32_t sz = 0;
            if (idx < 1584) {
                int ci = idx / 528; int r = idx - ci*528;
                int iy = r / 24, ix = r - iy*24;
                int gy = oy0 - 3 + iy, gx = ox0 - 3 + ix;
                if (ix < 22 && gy >= 0 && gy < HW && gx >= 0 && gx < HW) {
                    gp = xb + ci*HW2 + gy*HW + gx;
                    sz = 4;
                }
            }
            cp_async4(saddr, gp, sz);
        }
        asm volatile("cp.async.commit_group;" ::: "memory");
    };

    issue_halo(0, 0);

    for (int t = 0; t < C1_TPC; ++t) {
        int ox0 = oxbase + t*16;
        asm volatile("cp.async.wait_group 0;" ::: "memory");
        __syncthreads();     // hbuf[t&1] ready; prev-tile hp reads done

        {
            const float* hb = hbuf + (t & 1)*1992;
            for (int idx = tid; idx < 1984; idx += 256) {
                __half2 p = __floats2half2_rn(hb[idx], hb[idx+1]);
                hp[idx] = *(uint32_t*)&p;
            }
        }
        __syncthreads();     // hp ready

        if (t + 1 < C1_TPC) issue_halo(t + 1, (t + 1) & 1);
        else asm volatile("cp.async.commit_group;" ::: "memory");

        float d[2][8][4];
        #pragma unroll
        for (int i = 0; i < 2; ++i)
            #pragma unroll
            for (int j = 0; j < 8; ++j)
                #pragma unroll
                for (int q = 0; q < 4; ++q) d[i][j][q] = 0.f;

        #pragma unroll 4
        for (int kc = 0; kc < 12; ++kc) {
            int klo = (kc >> 2)*528 + (kc & 3)*48 + 2*ac;
            int khi = klo + 24;
            uint32_t a[2][4];
            a[0][0] = hp[bo0 + klo];
            a[0][1] = hp[bo1 + klo];
            a[0][2] = hp[bo0 + khi];
            a[0][3] = hp[bo1 + khi];
            a[1][0] = hp[bo2 + klo];
            a[1][1] = hp[bo3 + klo];
            a[1][2] = hp[bo2 + khi];
            a[1][3] = hp[bo3 + khi];
            uint32_t bf[8][2];
            #pragma unroll
            for (int jp = 0; jp < 4; ++jp) {
                uint4 wv = ((const uint4*)sW)[(kc*4 + jp)*32 + lane];
                bf[2*jp  ][0] = wv.x; bf[2*jp  ][1] = wv.y;
                bf[2*jp+1][0] = wv.z; bf[2*jp+1][1] = wv.w;
            }
            #pragma unroll
            for (int i = 0; i < 2; ++i)
                #pragma unroll
                for (int j = 0; j < 8; ++j)
                    mma_f16(d[i][j], a[i], bf[j]);
        }

        // direct channel-last fp16 store (no smem staging)
        #pragma unroll
        for (int i = 0; i < 2; ++i) {
            #pragma unroll
            for (int rr = 0; rr < 2; ++rr) {
                int p = m0 + 16*i + 8*rr + lq;
                int py = p >> 4, px = p & 15;
                __half* ob = g_t1h + ((size_t)img*HW2 + (size_t)(oy0 + py)*HW + (ox0 + px))*64;
                #pragma unroll
                for (int j = 0; j < 8; ++j) {
                    int oc = 8*j + 2*ac;
                    __half2 hv = __floats2half2_rn(d[i][j][2*rr + 0] + bv[j].x,
                                                   d[i][j][2*rr + 1] + bv[j].y);
                    *(__half2*)(ob + oc) = hv;
                }
            }
        }
    }
}

// ---------------- conv2: 3x3, 64->2, pad 1 via fp16 mma.sync ----------------
__global__ __launch_bounds__(256) void k_conv2(const float* __restrict__ b2) {
    __shared__ __half sH[10*1296];        // halo [hy][hx(stride 72)][ci]
    __shared__ uint32_t sBf[36*64];       // B fragments
    __shared__ float sb2[2];
    int tid = threadIdx.x;
    int img = blockIdx.z;
    int oy0 = blockIdx.y*8, ox0 = blockIdx.x*16;

    if (tid < 2) sb2[tid] = b2[tid];
    for (int i = tid; i < 36*64; i += 256) sBf[i] = g_w2frag[i];
    for (int i = tid; i < 1440; i += 256) {
        int cg = i & 7; int rest = i >> 3;
        int hxp = rest % 18, hy = rest / 18;
        int gy = oy0 - 1 + hy, gx = ox0 - 1 + hxp;
        uint4 v = make_uint4(0,0,0,0);
        if (gy >= 0 && gy < HW && gx >= 0 && gx < HW)
            v = *(const uint4*)(g_t1h + ((size_t)img*HW2 + (size_t)gy*HW + gx)*64 + cg*8);
        *(uint4*)&sH[hy*1296 + hxp*72 + cg*8] = v;
    }
    __syncthreads();

    int wid = tid >> 5, lane = tid & 31;
    int ac = lane & 3, lq = lane >> 2;
    float d[4] = {0.f, 0.f, 0.f, 0.f};

    #pragma unroll
    for (int kc = 0; kc < 36; ++kc) {
        int tap = kc >> 2;
        int kh = tap/3, kw = tap - kh*3;
        int cig = (kc & 3)*16;
        int hy = wid + kh;
        int base = hy*1296 + kw*72 + cig + 2*ac;
        uint32_t a[4];
        a[0] = *(const uint32_t*)&sH[base + lq*72];
        a[1] = *(const uint32_t*)&sH[base + (lq+8)*72];
        a[2] = *(const uint32_t*)&sH[base + lq*72 + 8];
        a[3] = *(const uint32_t*)&sH[base + (lq+8)*72 + 8];
        uint2 bb = *(const uint2*)&sBf[kc*64 + lane*2];
        uint32_t bf[2] = {bb.x, bb.y};
        mma_f16(d, a, bf);
    }

    if (ac == 0) {
        float* o0 = g_ini + ((size_t)img*2 + 0)*HW2;
        float* o1 = g_ini + ((size_t)img*2 + 1)*HW2;
        int gy = oy0 + wid;
        int g0 = gy*HW + ox0 + lq;
        o0[g0]     = d[0] + sb2[0];
        o1[g0]     = d[1] + sb2[1];
        o0[g0 + 8] = d[2] + sb2[0];
        o1[g0 + 8] = d[3] + sb2[1];
    }
}

// ---------------- fea: 1x1 conv 3->2, /4, vectorized ----------------
__global__ __launch_bounds__(256) void k_fea(const float* __restrict__ x,
        const float* __restrict__ wfm, const float* __restrict__ bfm) {
    int idx = blockIdx.x*256 + threadIdx.x;
    int img = idx / (HW2/4);
    int p4 = (idx - img*(HW2/4)) * 4;
    const float* xb = x + (size_t)img*CIN*HW2 + p4;
    float4 x0 = *(const float4*)xb;
    float4 x1 = *(const float4*)(xb + HW2);
    float4 x2 = *(const float4*)(xb + 2*HW2);
    #pragma unroll
    for (int c = 0; c < 2; ++c) {
        float f0 = wfm[c*3+0], f1 = wfm[c*3+1], f2 = wfm[c*3+2], fb = bfm[c];
        float4 o;
        o.x = (x0.x*f0 + x1.x*f1 + x2.x*f2 + fb)*0.25f;
        o.y = (x0.y*f0 + x1.y*f1 + x2.y*f2 + fb)*0.25f;
        o.z = (x0.z*f0 + x1.z*f1 + x2.z*f2 + fb)*0.25f;
        o.w = (x0.w*f0 + x1.w*f1 + x2.w*f2 + fb)*0.25f;
        *(float4*)(g_fea + ((size_t)img*2 + c)*HW2 + p4) = o;
    }
}

// ---------------- trans: relu(M @ v) per patch, via mma.sync, fp16 out ----------------
#define TR_STR 108
#define TR_SMEM ((104*TR_STR + 128*TR_STR)*4)

template<int J0, int NJ>
__device__ __forceinline__ void trans_warp(const uint32_t* uBM, const uint32_t* uA,
                                           __half* db, int m0, int lq, int ac) {
    float d[2][NJ][4];
    #pragma unroll
    for (int i = 0; i < 2; ++i)
        #pragma unroll
        for (int j = 0; j < NJ; ++j)
            #pragma unroll
            for (int q = 0; q < 4; ++q) d[i][j][q] = 0.f;

    #pragma unroll
    for (int kc = 0; kc < 13; ++kc) {
        int k0 = kc*8;
        uint32_t a[2][4], bf[NJ][2];
        #pragma unroll
        for (int i = 0; i < 2; ++i) {
            const uint32_t* base = uA + (m0 + 16*i + lq)*TR_STR + k0 + ac;
            a[i][0] = base[0];
            a[i][1] = base[8*TR_STR];
            a[i][2] = base[4];
            a[i][3] = base[8*TR_STR + 4];
        }
        #pragma unroll
        for (int j = 0; j < NJ; ++j) {
            const uint32_t* base = uBM + (8*(J0 + j) + lq)*TR_STR + k0 + ac;
            bf[j][0] = base[0];
            bf[j][1] = base[4];
        }
        #pragma unroll
        for (int i = 0; i < 2; ++i)
            #pragma unroll
            for (int j = 0; j < NJ; ++j)
                mma_tf32(d[i][j], a[i], bf[j]);
    }

    #pragma unroll
    for (int i = 0; i < 2; ++i) {
        #pragma unroll
        for (int rr = 0; rr < 2; ++rr) {
            int row = m0 + 16*i + lq + 8*rr;
            #pragma unroll
            for (int j = 0; j < NJ; ++j) {
                int col = 8*(J0 + j) + 2*ac;
                __half2 hv = __floats2half2_rn(fmaxf(d[i][j][2*rr + 0], 0.f),
                                               fmaxf(d[i][j][2*rr + 1], 0.f));
                *(uint32_t*)&db[(size_t)row*P2P + col] = *(uint32_t*)&hv;
            }
        }
    }
}

__global__ __launch_bounds__(256) void k_trans() {
    extern __shared__ uint32_t smt[];
    uint32_t* uBM = smt;
    uint32_t* uA  = smt + 104*TR_STR;
    int tid = threadIdx.x;
    int img = blockIdx.y;
    int l0 = blockIdx.x * 128;
    const float* src = (blockIdx.z == 0) ? g_ini : g_fea;
    __half* dst = (blockIdx.z == 0) ? g_UI : g_UF;

    for (int idx = tid; idx < 104*104; idx += 256) {
        int p = idx / 104, k = idx - p*104;
        uBM[p*TR_STR + k] = (p < P2 && k < P2) ? g_M[p*P2 + k] : 0u;
    }
    const float* sb = src + img*HW2;
    for (int idx = tid; idx < 128*104; idx += 256) {
        int pi = idx / 104, k = idx - pi*104;
        float v = 0.f;
        if (k < P2) {
            int l = l0 + pi;
            int py = k / PS, px = k - py*PS;
            v = sb[((l >> 5)*PS + py)*HW + (l & 31)*PS + px];
        }
        uA[pi*TR_STR + k] = f2tf32(v);
    }
    __syncthreads();

    int wid = tid >> 5, lane = tid & 31;
    int m0 = (wid & 3) * 32;
    int ac = lane & 3, lq = lane >> 2;
    __half* db = dst + (size_t)img*NPATCH*P2P + (size_t)l0*P2P;
    // zero K-pad cols 104..111 (as uint32: 4 per row)
    {
        uint32_t* d32 = (uint32_t*)db;
        for (int idx = tid; idx < 128*4; idx += 256)
            d32[(idx >> 2)*56 + 52 + (idx & 3)] = 0u;
    }
    if (wid < 4) trans_warp<0, 7>(uBM, uA, db, m0, lq, ac);
    else         trans_warp<7, 6>(uBM, uA, db, m0, lq, ac);
}

// ---------------- att: batched 1024x1024x112 NT-GEMM via fp16 mma.sync, /100 ----------------
#define AT_STR 68            // uint32 stride; 68 mod 32 == 4 -> conflict-free fragments
#define ATT_SMEM (2*128*AT_STR*4)
__global__ __launch_bounds__(256) void k_att(float* __restrict__ out) {
    extern __shared__ uint32_t sma[];
    uint32_t* sA = sma;
    uint32_t* sB = sma + 128*AT_STR;
    int tid = threadIdx.x;
    int wid = tid >> 5, lane = tid & 31;
    int img = blockIdx.z;
    int gl0 = blockIdx.y*128, gm0 = blockIdx.x*128;
    const __half* UI = g_UI + (size_t)img*NPATCH*P2P;
    const __half* UF = g_UF + (size_t)img*NPATCH*P2P;

    for (int it = tid; it < 128*14; it += 256) {
        int rr = it/14, c = it - rr*14;
        uint4 va = *(const uint4*)&UI[(size_t)(gl0 + rr)*P2P + c*8];
        *(uint4*)&sA[rr*AT_STR + c*4] = va;
        uint4 vb = *(const uint4*)&UF[(size_t)(gm0 + rr)*P2P + c*8];
        *(uint4*)&sB[rr*AT_STR + c*4] = vb;
    }
    __syncthreads();

    int m0 = (wid & 3)*32, n0 = (wid >> 2)*64;
    int ac = lane & 3, lq = lane >> 2;
    float d[2][8][4];
    #pragma unroll
    for (int i = 0; i < 2; ++i)
        #pragma unroll
        for (int j = 0; j < 8; ++j)
            #pragma unroll
            for (int q = 0; q < 4; ++q) d[i][j][q] = 0.f;

    #pragma unroll
    for (int kc = 0; kc < 7; ++kc) {
        int k0 = kc*8;
        uint32_t a[2][4], bf[8][2];
        #pragma unroll
        for (int i = 0; i < 2; ++i) {
            const uint32_t* base = sA + (m0 + 16*i + lq)*AT_STR + k0 + ac;
            a[i][0] = base[0];
            a[i][1] = base[8*AT_STR];
            a[i][2] = base[4];
            a[i][3] = base[8*AT_STR + 4];
        }
        #pragma unroll
        for (int j = 0; j < 8; ++j) {
            const uint32_t* base = sB + (n0 + 8*j + lq)*AT_STR + k0 + ac;
            bf[j][0] = base[0];
            bf[j][1] = base[4];
        }
        #pragma unroll
        for (int i = 0; i < 2; ++i)
            #pragma unroll
            for (int j = 0; j < 8; ++j)
                mma_f16(d[i][j], a[i], bf[j]);
    }

    #pragma unroll
    for (int i = 0; i < 2; ++i) {
        #pragma unroll
        for (int rr = 0; rr < 2; ++rr) {
            int l = gl0 + m0 + 16*i + lq + 8*rr;
            #pragma unroll
            for (int j = 0; j < 8; ++j) {
                int m = gm0 + n0 + 8*j + 2*ac;
                float2 v = make_float2(d[i][j][2*rr + 0]*0.01f, d[i][j][2*rr + 1]*0.01f);
                *(float2*)&out[((long)img*NPATCH + l)*NPATCH + m] = v;
            }
        }
    }
}

extern "C" void kernel_launch(void* const* d_in, const int* in_sizes, int n_in,
                              void* d_out, int out_size) {
    const float* x   = (const float*)d_in[0];
    const float* w1c = (const float*)d_in[1];
    const float* b1c = (const float*)d_in[2];
    const float* w2c = (const float*)d_in[3];
    const float* b2c = (const float*)d_in[4];
    const float* wfm = (const float*)d_in[5];
    const float* bfm = (const float*)d_in[6];
    const float* wl1 = (const float*)d_in[7];
    const float* wl2 = (const float*)d_in[8];
    float* out = (float*)d_out;

    static bool attr_set = false;
    if (!attr_set) {
        cudaFuncSetAttribute(k_conv1, cudaFuncAttributeMaxDynamicSharedMemorySize, C1_SMEMB);
        cudaFuncSetAttribute(k_trans, cudaFuncAttributeMaxDynamicSharedMemorySize, TR_SMEM);
        cudaFuncSetAttribute(k_att,   cudaFuncAttributeMaxDynamicSharedMemorySize, ATT_SMEM);
        attr_set = true;
    }

    k_buildM<<<P2, 128>>>(wl1, wl2);
    k_prepw<<<24, 256>>>(w1c);
    k_prepw2<<<9, 256>>>(w2c);
    k_conv1<<<dim3(5,20,BATCH), 256, C1_SMEMB>>>(x, b1c);
    k_conv2<<<dim3(20,40,BATCH), 256>>>(b2c);
    k_fea<<<800, 256>>>(x, wfm, bfm);
    k_trans<<<dim3(8, IMGS, 2), 256, TR_SMEM>>>();
    k_att<<<dim3(8,8,IMGS), 256, ATT_SMEM>>>(out);
}

// round 11
// speedup vs baseline: 7.8456x; 1.6800x over previous
#include <cuda_runtime.h>
#include <cuda_fp16.h>
#include <cstdint>

#define BATCH 8
#define CIN 3
#define HW 320
#define HW2 (HW*HW)
#define C1 64
#define PS 10
#define P2 100
#define P2P 112
#define NPATCH 1024
#define IMGS 16

// scratch (device globals — no runtime allocation)
__device__ float g_ini[IMGS*HW2];
__device__ float g_fea[IMGS*HW2];
__device__ uint32_t g_M[P2*P2];                  // (W2@W1) row-major [p][k], tf32 bits
__device__ float g_Wc[486];                      // composed 9x9 conv: [((ci*9+uy)*9+ux)*2+c]
__device__ float g_Wp[2646];                     // per-tap composed 7x7: [((t*2+c)*3+ci)*49+s]
__device__ float g_s2[18];                       // [c*9+t] = w2[t]·b1
__device__ float g_B[2];                         // full bias
__device__ __half g_UI[(size_t)IMGS*NPATCH*P2P]; // fp16, K padded to 112
__device__ __half g_UF[(size_t)IMGS*NPATCH*P2P];

// ---------------- helpers ----------------
__device__ __forceinline__ uint32_t f2tf32(float f) {
    uint32_t r;
    asm("cvt.rna.tf32.f32 %0, %1;" : "=r"(r) : "f"(f));
    return r;
}
__device__ __forceinline__ void mma_tf32(float* d, const uint32_t* a, const uint32_t* b) {
    asm volatile(
        "mma.sync.aligned.m16n8k8.row.col.f32.tf32.tf32.f32 "
        "{%0,%1,%2,%3}, {%4,%5,%6,%7}, {%8,%9}, {%0,%1,%2,%3};"
        : "+f"(d[0]), "+f"(d[1]), "+f"(d[2]), "+f"(d[3])
        : "r"(a[0]), "r"(a[1]), "r"(a[2]), "r"(a[3]), "r"(b[0]), "r"(b[1]));
}
__device__ __forceinline__ void mma_f16(float* d, const uint32_t* a, const uint32_t* b) {
    asm volatile(
        "mma.sync.aligned.m16n8k16.row.col.f32.f16.f16.f32 "
        "{%0,%1,%2,%3}, {%4,%5,%6,%7}, {%8,%9}, {%0,%1,%2,%3};"
        : "+f"(d[0]), "+f"(d[1]), "+f"(d[2]), "+f"(d[3])
        : "r"(a[0]), "r"(a[1]), "r"(a[2]), "r"(a[3]), "r"(b[0]), "r"(b[1]));
}

// ---------------- M = w_lin2 @ w_lin1 (row-major [p][k], tf32 bits) ----------------
__global__ void k_buildM(const float* __restrict__ w1, const float* __restrict__ w2) {
    int p = blockIdx.x;
    int k = threadIdx.x;
    if (k >= P2) return;
    float acc = 0.f;
    for (int q = 0; q < 2*P2; ++q)
        acc += w2[p*2*P2 + q] * w1[q*P2 + k];
    g_M[p*P2 + k] = f2tf32(acc);
}

// ---------------- compose conv2 o conv1 -> 9x9 kernel + per-tap 7x7 + bias terms ----------------
__global__ void k_compose(const float* __restrict__ w1, const float* __restrict__ b1,
                          const float* __restrict__ w2, const float* __restrict__ b2) {
    int idx = blockIdx.x*256 + threadIdx.x;
    if (idx < 486) {
        // Wc[c][ci][uy][ux] = sum_{ty,tx,m} w2[c][m][ty][tx] * w1[m][ci][uy-ty][ux-tx]
        int c = idx / 243; int r = idx - c*243;
        int ci = r / 81; int r2 = r - ci*81;
        int uy = r2 / 9, ux = r2 - (r2/9)*9;
        float acc = 0.f;
        for (int ty = 0; ty < 3; ++ty) {
            int sy = uy - ty; if (sy < 0 || sy > 6) continue;
            for (int tx = 0; tx < 3; ++tx) {
                int sx = ux - tx; if (sx < 0 || sx > 6) continue;
                for (int m = 0; m < 64; ++m)
                    acc += w2[((c*64 + m)*3 + ty)*3 + tx] * w1[((m*3 + ci)*7 + sy)*7 + sx];
            }
        }
        g_Wc[((ci*9 + uy)*9 + ux)*2 + c] = acc;
    } else if (idx < 486 + 2646) {
        // Wp[t][c][ci][s] = sum_m w2[c][m][t] * w1[m][ci][s]
        int j = idx - 486;
        int t = j / 294; int r = j - t*294;
        int c = r / 147; int r2 = r - c*147;
        int ci = r2 / 49; int s = r2 - ci*49;
        int ty = t / 3, tx = t - ty*3;
        int sy = s / 7, sx = s - sy*7;
        float acc = 0.f;
        for (int m = 0; m < 64; ++m)
            acc += w2[((c*64 + m)*3 + ty)*3 + tx] * w1[((m*3 + ci)*7 + sy)*7 + sx];
        g_Wp[j] = acc;
    } else if (idx < 486 + 2646 + 18) {
        int j = idx - 3132;
        int c = j / 9, t = j - (j/9)*9;
        int ty = t / 3, tx = t - ty*3;
        float acc = 0.f;
        for (int m = 0; m < 64; ++m)
            acc += w2[((c*64 + m)*3 + ty)*3 + tx] * b1[m];
        g_s2[j] = acc;
    } else if (idx < 486 + 2646 + 18 + 2) {
        int c = idx - 3150;
        float acc = b2[c];
        for (int t = 0; t < 9; ++t) {
            int ty = t / 3, tx = t - ty*3;
            float s = 0.f;
            for (int m = 0; m < 64; ++m)
                s += w2[((c*64 + m)*3 + ty)*3 + tx] * b1[m];
            acc += s;
        }
        g_B[c] = acc;
    }
}

// ---------------- ini = composed 9x9 conv (3->2) + exact border-ring fixup ----------------
__global__ __launch_bounds__(256) void k_ini(const float* __restrict__ x) {
    __shared__ float sx[3*40*40];
    __shared__ float sWc[486];
    __shared__ float sWp[2646];
    __shared__ float sS[18];
    __shared__ float sB[2];
    int tid = threadIdx.x;
    int img = blockIdx.z;
    int oy0 = blockIdx.y*32, ox0 = blockIdx.x*32;

    const float* xb = x + (size_t)img*CIN*HW2;
    for (int idx = tid; idx < 4800; idx += 256) {
        int ci = idx / 1600; int r = idx - ci*1600;
        int iy = r / 40, ix = r - iy*40;
        int gy = oy0 - 4 + iy, gx = ox0 - 4 + ix;
        float v = 0.f;
        if (gy >= 0 && gy < HW && gx >= 0 && gx < HW)
            v = xb[ci*HW2 + gy*HW + gx];
        sx[idx] = v;
    }
    for (int idx = tid; idx < 486; idx += 256) sWc[idx] = g_Wc[idx];
    for (int idx = tid; idx < 2646; idx += 256) sWp[idx] = g_Wp[idx];
    if (tid < 18) sS[tid] = g_s2[tid];
    if (tid < 2) sB[tid] = g_B[tid];
    __syncthreads();

    int row = tid >> 3;
    int xq = (tid & 7) * 4;
    float acc0[4], acc1[4];
    #pragma unroll
    for (int dx = 0; dx < 4; ++dx) { acc0[dx] = sB[0]; acc1[dx] = sB[1]; }

    #pragma unroll 1
    for (int ci = 0; ci < 3; ++ci) {
        #pragma unroll
        for (int uy = 0; uy < 9; ++uy) {
            const float* rp = &sx[ci*1600 + (row + uy)*40 + xq];
            float4 v0 = *(const float4*)rp;
            float4 v1 = *(const float4*)(rp + 4);
            float4 v2 = *(const float4*)(rp + 8);
            float vv[12] = {v0.x, v0.y, v0.z, v0.w, v1.x, v1.y, v1.z, v1.w,
                            v2.x, v2.y, v2.z, v2.w};
            const float2* wp = (const float2*)&sWc[(ci*9 + uy)*9*2];
            #pragma unroll
            for (int ux = 0; ux < 9; ++ux) {
                float2 w = wp[ux];
                #pragma unroll
                for (int dx = 0; dx < 4; ++dx) {
                    acc0[dx] += vv[ux + dx] * w.x;
                    acc1[dx] += vv[ux + dx] * w.y;
                }
            }
        }
    }

    // exact border-ring fixup (1-pixel ring: conv2's zero-pad vs composed assumption)
    int y = oy0 + row;
    bool edge_tile = (oy0 == 0) | (oy0 == HW - 32) | (ox0 == 0) | (ox0 == HW - 32);
    if (edge_tile) {
        #pragma unroll 1
        for (int dx = 0; dx < 4; ++dx) {
            int xg = ox0 + xq + dx;
            if (y != 0 && y != HW-1 && xg != 0 && xg != HW-1) continue;
            for (int t = 0; t < 9; ++t) {
                int ty = t / 3, tx = t - ty*3;
                int py = y + ty - 1, px = xg + tx - 1;
                if (py >= 0 && py < HW && px >= 0 && px < HW) continue;
                acc0[dx] -= sS[t];
                acc1[dx] -= sS[9 + t];
                for (int ci = 0; ci < 3; ++ci)
                    for (int sy = 0; sy < 7; ++sy)
                        for (int sx7 = 0; sx7 < 7; ++sx7) {
                            float v = sx[ci*1600 + (row + ty + sy)*40 + (xq + dx + tx + sx7)];
                            acc0[dx] -= v * sWp[((t*2 + 0)*3 + ci)*49 + sy*7 + sx7];
                            acc1[dx] -= v * sWp[((t*2 + 1)*3 + ci)*49 + sy*7 + sx7];
                        }
            }
        }
    }

    size_t ob = ((size_t)img*2)*HW2 + (size_t)y*HW + ox0 + xq;
    *(float4*)&g_ini[ob]       = make_float4(acc0[0], acc0[1], acc0[2], acc0[3]);
    *(float4*)&g_ini[ob + HW2] = make_float4(acc1[0], acc1[1], acc1[2], acc1[3]);
}

// ---------------- fea: 1x1 conv 3->2, /4, vectorized ----------------
__global__ __launch_bounds__(256) void k_fea(const float* __restrict__ x,
        const float* __restrict__ wfm, const float* __restrict__ bfm) {
    int idx = blockIdx.x*256 + threadIdx.x;
    int img = idx / (HW2/4);
    int p4 = (idx - img*(HW2/4)) * 4;
    const float* xb = x + (size_t)img*CIN*HW2 + p4;
    float4 x0 = *(const float4*)xb;
    float4 x1 = *(const float4*)(xb + HW2);
    float4 x2 = *(const float4*)(xb + 2*HW2);
    #pragma unroll
    for (int c = 0; c < 2; ++c) {
        float f0 = wfm[c*3+0], f1 = wfm[c*3+1], f2 = wfm[c*3+2], fb = bfm[c];
        float4 o;
        o.x = (x0.x*f0 + x1.x*f1 + x2.x*f2 + fb)*0.25f;
        o.y = (x0.y*f0 + x1.y*f1 + x2.y*f2 + fb)*0.25f;
        o.z = (x0.z*f0 + x1.z*f1 + x2.z*f2 + fb)*0.25f;
        o.w = (x0.w*f0 + x1.w*f1 + x2.w*f2 + fb)*0.25f;
        *(float4*)(g_fea + ((size_t)img*2 + c)*HW2 + p4) = o;
    }
}

// ---------------- trans: relu(M @ v) per patch, via mma.sync, fp16 out ----------------
#define TR_STR 108
#define TR_SMEM ((104*TR_STR + 128*TR_STR)*4)

template<int J0, int NJ>
__device__ __forceinline__ void trans_warp(const uint32_t* uBM, const uint32_t* uA,
                                           __half* db, int m0, int lq, int ac) {
    float d[2][NJ][4];
    #pragma unroll
    for (int i = 0; i < 2; ++i)
        #pragma unroll
        for (int j = 0; j < NJ; ++j)
            #pragma unroll
            for (int q = 0; q < 4; ++q) d[i][j][q] = 0.f;

    #pragma unroll
    for (int kc = 0; kc < 13; ++kc) {
        int k0 = kc*8;
        uint32_t a[2][4], bf[NJ][2];
        #pragma unroll
        for (int i = 0; i < 2; ++i) {
            const uint32_t* base = uA + (m0 + 16*i + lq)*TR_STR + k0 + ac;
            a[i][0] = base[0];
            a[i][1] = base[8*TR_STR];
            a[i][2] = base[4];
            a[i][3] = base[8*TR_STR + 4];
        }
        #pragma unroll
        for (int j = 0; j < NJ; ++j) {
            const uint32_t* base = uBM + (8*(J0 + j) + lq)*TR_STR + k0 + ac;
            bf[j][0] = base[0];
            bf[j][1] = base[4];
        }
        #pragma unroll
        for (int i = 0; i < 2; ++i)
            #pragma unroll
            for (int j = 0; j < NJ; ++j)
                mma_tf32(d[i][j], a[i], bf[j]);
    }

    #pragma unroll
    for (int i = 0; i < 2; ++i) {
        #pragma unroll
        for (int rr = 0; rr < 2; ++rr) {
            int row = m0 + 16*i + lq + 8*rr;
            #pragma unroll
            for (int j = 0; j < NJ; ++j) {
                int col = 8*(J0 + j) + 2*ac;
                __half2 hv = __floats2half2_rn(fmaxf(d[i][j][2*rr + 0], 0.f),
                                               fmaxf(d[i][j][2*rr + 1], 0.f));
                *(uint32_t*)&db[(size_t)row*P2P + col] = *(uint32_t*)&hv;
            }
        }
    }
}

__global__ __launch_bounds__(256) void k_trans() {
    extern __shared__ uint32_t smt[];
    uint32_t* uBM = smt;
    uint32_t* uA  = smt + 104*TR_STR;
    int tid = threadIdx.x;
    int img = blockIdx.y;
    int l0 = blockIdx.x * 128;
    const float* src = (blockIdx.z == 0) ? g_ini : g_fea;
    __half* dst = (blockIdx.z == 0) ? g_UI : g_UF;

    for (int idx = tid; idx < 104*104; idx += 256) {
        int p = idx / 104, k = idx - p*104;
        uBM[p*TR_STR + k] = (p < P2 && k < P2) ? g_M[p*P2 + k] : 0u;
    }
    const float* sb = src + img*HW2;
    for (int idx = tid; idx < 128*104; idx += 256) {
        int pi = idx / 104, k = idx - pi*104;
        float v = 0.f;
        if (k < P2) {
            int l = l0 + pi;
            int py = k / PS, px = k - py*PS;
            v = sb[((l >> 5)*PS + py)*HW + (l & 31)*PS + px];
        }
        uA[pi*TR_STR + k] = f2tf32(v);
    }
    __syncthreads();

    int wid = tid >> 5, lane = tid & 31;
    int m0 = (wid & 3) * 32;
    int ac = lane & 3, lq = lane >> 2;
    __half* db = dst + (size_t)img*NPATCH*P2P + (size_t)l0*P2P;
    // zero K-pad cols 104..111 (as uint32: 4 per row)
    {
        uint32_t* d32 = (uint32_t*)db;
        for (int idx = tid; idx < 128*4; idx += 256)
            d32[(idx >> 2)*56 + 52 + (idx & 3)] = 0u;
    }
    if (wid < 4) trans_warp<0, 7>(uBM, uA, db, m0, lq, ac);
    else         trans_warp<7, 6>(uBM, uA, db, m0, lq, ac);
}

// ---------------- att: batched 1024x1024x112 NT-GEMM via fp16 mma.sync, /100 ----------------
#define AT_STR 68            // uint32 stride; 68 mod 32 == 4 -> conflict-free fragments
#define ATT_SMEM (2*128*AT_STR*4)
__global__ __launch_bounds__(256) void k_att(float* __restrict__ out) {
    extern __shared__ uint32_t sma[];
    uint32_t* sA = sma;
    uint32_t* sB = sma + 128*AT_STR;
    int tid = threadIdx.x;
    int wid = tid >> 5, lane = tid & 31;
    int img = blockIdx.z;
    int gl0 = blockIdx.y*128, gm0 = blockIdx.x*128;
    const __half* UI = g_UI + (size_t)img*NPATCH*P2P;
    const __half* UF = g_UF + (size_t)img*NPATCH*P2P;

    for (int it = tid; it < 128*14; it += 256) {
        int rr = it/14, c = it - rr*14;
        uint4 va = *(const uint4*)&UI[(size_t)(gl0 + rr)*P2P + c*8];
        *(uint4*)&sA[rr*AT_STR + c*4] = va;
        uint4 vb = *(const uint4*)&UF[(size_t)(gm0 + rr)*P2P + c*8];
        *(uint4*)&sB[rr*AT_STR + c*4] = vb;
    }
    __syncthreads();

    int m0 = (wid & 3)*32, n0 = (wid >> 2)*64;
    int ac = lane & 3, lq = lane >> 2;
    float d[2][8][4];
    #pragma unroll
    for (int i = 0; i < 2; ++i)
        #pragma unroll
        for (int j = 0; j < 8; ++j)
            #pragma unroll
            for (int q = 0; q < 4; ++q) d[i][j][q] = 0.f;

    #pragma unroll
    for (int kc = 0; kc < 7; ++kc) {
        int k0 = kc*8;
        uint32_t a[2][4], bf[8][2];
        #pragma unroll
        for (int i = 0; i < 2; ++i) {
            const uint32_t* base = sA + (m0 + 16*i + lq)*AT_STR + k0 + ac;
            a[i][0] = base[0];
            a[i][1] = base[8*AT_STR];
            a[i][2] = base[4];
            a[i][3] = base[8*AT_STR + 4];
        }
        #pragma unroll
        for (int j = 0; j < 8; ++j) {
            const uint32_t* base = sB + (n0 + 8*j + lq)*AT_STR + k0 + ac;
            bf[j][0] = base[0];
            bf[j][1] = base[4];
        }
        #pragma unroll
        for (int i = 0; i < 2; ++i)
            #pragma unroll
            for (int j = 0; j < 8; ++j)
                mma_f16(d[i][j], a[i], bf[j]);
    }

    #pragma unroll
    for (int i = 0; i < 2; ++i) {
        #pragma unroll
        for (int rr = 0; rr < 2; ++rr) {
            int l = gl0 + m0 + 16*i + lq + 8*rr;
            #pragma unroll
            for (int j = 0; j < 8; ++j) {
                int m = gm0 + n0 + 8*j + 2*ac;
                float2 v = make_float2(d[i][j][2*rr + 0]*0.01f, d[i][j][2*rr + 1]*0.01f);
                *(float2*)&out[((long)img*NPATCH + l)*NPATCH + m] = v;
            }
        }
    }
}

extern "C" void kernel_launch(void* const* d_in, const int* in_sizes, int n_in,
                              void* d_out, int out_size) {
    const float* x   = (const float*)d_in[0];
    const float* w1c = (const float*)d_in[1];
    const float* b1c = (const float*)d_in[2];
    const float* w2c = (const float*)d_in[3];
    const float* b2c = (const float*)d_in[4];
    const float* wfm = (const float*)d_in[5];
    const float* bfm = (const float*)d_in[6];
    const float* wl1 = (const float*)d_in[7];
    const float* wl2 = (const float*)d_in[8];
    float* out = (float*)d_out;

    static bool attr_set = false;
    if (!attr_set) {
        cudaFuncSetAttribute(k_trans, cudaFuncAttributeMaxDynamicSharedMemorySize, TR_SMEM);
        cudaFuncSetAttribute(k_att,   cudaFuncAttributeMaxDynamicSharedMemorySize, ATT_SMEM);
        attr_set = true;
    }

    k_buildM<<<P2, 128>>>(wl1, wl2);
    k_compose<<<13, 256>>>(w1c, b1c, w2c, b2c);
    k_ini<<<dim3(10,10,BATCH), 256>>>(x);
    k_fea<<<800, 256>>>(x, wfm, bfm);
    k_trans<<<dim3(8, IMGS, 2), 256, TR_SMEM>>>();
    k_att<<<dim3(8,8,IMGS), 256, ATT_SMEM>>>(out);
}